// round 2
// baseline (speedup 1.0000x reference)
#include <cuda_runtime.h>
#include <math.h>

#define BB   128
#define TT   65536
#define DELTA 16
#define LS   32
#define HID  8
#define GH   64
#define ODIM 16
#define FF   4095            // (TT-LS)/DELTA + 1

#define CCH  256             // fast-branch chunk length (multiple of 16)
#define NCH  (TT/CCH)        // 256 chunks per batch row

#define SCOLS 256            // columns (sequences) per CTA in slow kernel

// ---------------- device scratch (static, allocation-free) ----------------
__device__ float d_As[(size_t)BB * FF * HID];   // sigmoid gates  (16.8 MB)
__device__ float d_gs[(size_t)BB * FF * HID];   // g gates        (16.8 MB)
__device__ float d_P [BB * NCH * HID];          // per-chunk A-products
__device__ float d_c [BB * NCH * HID];          // per-chunk offsets
__device__ float d_H0[BB * NCH * HID];          // per-chunk initial h
__device__ float d_cpar[GH * 8];                // packed per-j GRU constants

// ---------------- math helpers ----------------
__device__ __forceinline__ float sigf(float v) {
    return __fdividef(1.0f, 1.0f + __expf(-v));
}
__device__ __forceinline__ float tanh_f(float v) {
    v = fminf(fmaxf(v, -15.0f), 15.0f);
    float e = __expf(-2.0f * v);
    return __fdividef(1.0f - e, 1.0f + e);
}

// ---------------- init: pack per-j gate constants ----------------
__global__ void init_cpar_kernel(const float* __restrict__ w_ih,
                                 const float* __restrict__ b_ih,
                                 const float* __restrict__ b_hh) {
    int j = threadIdx.x;
    if (j < GH) {
        d_cpar[j*8+0] = w_ih[j];                       // w_ih r
        d_cpar[j*8+1] = w_ih[GH + j];                  // w_ih z
        d_cpar[j*8+2] = w_ih[2*GH + j];                // w_ih n
        d_cpar[j*8+3] = b_ih[j]      + b_hh[j];        // bias r (combined)
        d_cpar[j*8+4] = b_ih[GH + j] + b_hh[GH + j];   // bias z (combined)
        d_cpar[j*8+5] = b_ih[2*GH + j];                // b_ih n
        d_cpar[j*8+6] = b_hh[2*GH + j];                // b_hh n (inside r*(...))
        d_cpar[j*8+7] = 0.0f;
    }
}

// ---------------- slow branch: GRU, h kept in SMEM ----------------
// grid = ceil(FF/2) blocks, 256 threads. Thread = (frame-sub fi, batch b).
// h layout in smem: hbuf[k*SCOLS + col], col = threadIdx.x. Conflict-free.
// Smem floats: ws 12288 | h0 16384 | h1 16384 | cpar 512 | wsl 1024 | bsl 16
#define SM_WS   0
#define SM_H0   12288
#define SM_H1   (12288 + 64*SCOLS)
#define SM_CPAR (12288 + 2*64*SCOLS)
#define SM_WSL  (SM_CPAR + 512)
#define SM_BSL  (SM_WSL + ODIM*GH)
#define SM_FLOATS (SM_BSL + 16)

extern __shared__ float smem[];

__global__ void __launch_bounds__(SCOLS) slow_kernel(
    const float* __restrict__ x,
    const float* __restrict__ w_hh,
    const float* __restrict__ w_sl,
    const float* __restrict__ b_sl)
{
    const int tid = threadIdx.x;

    // cooperative loads into smem
    for (int i = tid; i < 3 * GH * GH; i += SCOLS) smem[SM_WS + i] = w_hh[i];
    for (int i = tid; i < GH * 8;     i += SCOLS) smem[SM_CPAR + i] = d_cpar[i];
    for (int i = tid; i < ODIM * GH;  i += SCOLS) smem[SM_WSL + i] = w_sl[i];
    if (tid < ODIM) smem[SM_BSL + tid] = b_sl[tid];
    // init h0 for own column
    for (int k = 0; k < GH; k++) smem[SM_H0 + k * SCOLS + tid] = 0.0f;
    __syncthreads();

    const int b  = tid & 127;
    const int fi = tid >> 7;
    const int f  = blockIdx.x * 2 + fi;
    const bool active = (f < FF);

    const float* xp = x + (size_t)b * TT + (size_t)(active ? f : 0) * DELTA;

    float* hc = smem + SM_H0 + tid;   // current h, stride SCOLS
    float* hn = smem + SM_H1 + tid;   // next h

    const float* ws   = smem + SM_WS;
    const float* cpar = smem + SM_CPAR;

    float xt = active ? xp[0] : 0.0f;

#pragma unroll 1
    for (int t = 0; t < LS; t++) {
        float xnext = (active && t < LS - 1) ? xp[t + 1] : 0.0f;

#pragma unroll 1
        for (int j = 0; j < GH; j += 2) {
            const float4* wr0 = (const float4*)(ws + (j    ) * GH);
            const float4* wr1 = (const float4*)(ws + (j + 1) * GH);
            const float4* wz0 = (const float4*)(ws + (GH + j    ) * GH);
            const float4* wz1 = (const float4*)(ws + (GH + j + 1) * GH);
            const float4* wn0 = (const float4*)(ws + (2*GH + j    ) * GH);
            const float4* wn1 = (const float4*)(ws + (2*GH + j + 1) * GH);

            float ar0 = 0.f, az0 = 0.f, an0 = 0.f;
            float ar1 = 0.f, az1 = 0.f, an1 = 0.f;
#pragma unroll
            for (int k4 = 0; k4 < 16; k4++) {
                float h0v = hc[(k4*4 + 0) * SCOLS];
                float h1v = hc[(k4*4 + 1) * SCOLS];
                float h2v = hc[(k4*4 + 2) * SCOLS];
                float h3v = hc[(k4*4 + 3) * SCOLS];
                float4 a = wr0[k4], bq = wz0[k4], c = wn0[k4];
                float4 d = wr1[k4], e = wz1[k4], g = wn1[k4];
                ar0 = fmaf(a.x, h0v, ar0); ar0 = fmaf(a.y, h1v, ar0);
                ar0 = fmaf(a.z, h2v, ar0); ar0 = fmaf(a.w, h3v, ar0);
                az0 = fmaf(bq.x, h0v, az0); az0 = fmaf(bq.y, h1v, az0);
                az0 = fmaf(bq.z, h2v, az0); az0 = fmaf(bq.w, h3v, az0);
                an0 = fmaf(c.x, h0v, an0); an0 = fmaf(c.y, h1v, an0);
                an0 = fmaf(c.z, h2v, an0); an0 = fmaf(c.w, h3v, an0);
                ar1 = fmaf(d.x, h0v, ar1); ar1 = fmaf(d.y, h1v, ar1);
                ar1 = fmaf(d.z, h2v, ar1); ar1 = fmaf(d.w, h3v, ar1);
                az1 = fmaf(e.x, h0v, az1); az1 = fmaf(e.y, h1v, az1);
                az1 = fmaf(e.z, h2v, az1); az1 = fmaf(e.w, h3v, az1);
                an1 = fmaf(g.x, h0v, an1); an1 = fmaf(g.y, h1v, an1);
                an1 = fmaf(g.z, h2v, an1); an1 = fmaf(g.w, h3v, an1);
            }
            // nonlinearity for j and j+1
            {
                const float4 c0 = ((const float4*)(cpar + j * 8))[0];
                const float4 c1 = ((const float4*)(cpar + j * 8))[1];
                float hold = hc[j * SCOLS];
                float r = sigf(fmaf(xt, c0.x, c0.w) + ar0);
                float z = sigf(fmaf(xt, c0.y, c1.x) + az0);
                float n = tanh_f(fmaf(xt, c0.z, c1.y) + r * (an0 + c1.z));
                hn[j * SCOLS] = n + z * (hold - n);
            }
            {
                const float4 c0 = ((const float4*)(cpar + (j+1) * 8))[0];
                const float4 c1 = ((const float4*)(cpar + (j+1) * 8))[1];
                float hold = hc[(j+1) * SCOLS];
                float r = sigf(fmaf(xt, c0.x, c0.w) + ar1);
                float z = sigf(fmaf(xt, c0.y, c1.x) + az1);
                float n = tanh_f(fmaf(xt, c0.z, c1.y) + r * (an1 + c1.z));
                hn[(j+1) * SCOLS] = n + z * (hold - n);
            }
        }
        // swap buffers (thread-private columns: no sync needed)
        float* tmp = hc; hc = hn; hn = tmp;
        xt = xnext;
    }

    // epilogue: eps = w_sl @ h + b_sl
    if (active) {
        const float* wsl = smem + SM_WSL;
        const float* bsl = smem + SM_BSL;
        const size_t base = ((size_t)b * FF + f) * HID;
#pragma unroll 1
        for (int o = 0; o < HID; o++) {
            float a0 = bsl[o];
            float a1 = bsl[HID + o];
            const float4* w0 = (const float4*)(wsl + o * GH);
            const float4* w1 = (const float4*)(wsl + (HID + o) * GH);
#pragma unroll
            for (int k4 = 0; k4 < 16; k4++) {
                float h0v = hc[(k4*4 + 0) * SCOLS];
                float h1v = hc[(k4*4 + 1) * SCOLS];
                float h2v = hc[(k4*4 + 2) * SCOLS];
                float h3v = hc[(k4*4 + 3) * SCOLS];
                float4 v0 = w0[k4], v1 = w1[k4];
                a0 = fmaf(v0.x, h0v, a0); a0 = fmaf(v0.y, h1v, a0);
                a0 = fmaf(v0.z, h2v, a0); a0 = fmaf(v0.w, h3v, a0);
                a1 = fmaf(v1.x, h0v, a1); a1 = fmaf(v1.y, h1v, a1);
                a1 = fmaf(v1.z, h2v, a1); a1 = fmaf(v1.w, h3v, a1);
            }
            d_As[base + o] = sigf(a0);
            d_gs[base + o] = a1;
        }
    }
}

// ---------------- fast branch pass 1: per-chunk (P, c) ----------------
__global__ void __launch_bounds__(256) pass1_kernel(
    const float* __restrict__ x, const float* __restrict__ w_in)
{
    int q = blockIdx.x * blockDim.x + threadIdx.x;
    if (q >= BB * NCH) return;
    int b = q / NCH;
    int ch = q % NCH;

    float win[HID];
#pragma unroll
    for (int i = 0; i < HID; i++) win[i] = w_in[i];

    float P[HID], c[HID];
#pragma unroll
    for (int i = 0; i < HID; i++) { P[i] = 1.0f; c[i] = 0.0f; }

    const int t0 = ch * CCH;
    const float* xb = x + (size_t)b * TT;

#pragma unroll 1
    for (int blk = 0; blk < CCH / 16; blk++) {
        int t = t0 + blk * 16;
        int j = (t >> 4) - 1; if (j < 0) j = 0;
        const float4* ap = (const float4*)(d_As + ((size_t)b * FF + j) * HID);
        const float4* gp = (const float4*)(d_gs + ((size_t)b * FF + j) * HID);
        float4 Aa = ap[0], Ab = ap[1];
        float4 ga = gp[0], gb = gp[1];
        float A[HID] = {Aa.x, Aa.y, Aa.z, Aa.w, Ab.x, Ab.y, Ab.z, Ab.w};
        float g[HID] = {ga.x, ga.y, ga.z, ga.w, gb.x, gb.y, gb.z, gb.w};
        float wg[HID], a16[HID];
#pragma unroll
        for (int i = 0; i < HID; i++) {
            wg[i] = win[i] * g[i];
            float a2 = A[i] * A[i];
            float a4 = a2 * a2;
            float a8 = a4 * a4;
            a16[i] = a8 * a8;
        }
        const float4* xv = (const float4*)(xb + t);
#pragma unroll
        for (int s4 = 0; s4 < 4; s4++) {
            float4 xq = xv[s4];
            float xs[4] = {xq.x, xq.y, xq.z, xq.w};
#pragma unroll
            for (int s = 0; s < 4; s++) {
#pragma unroll
                for (int i = 0; i < HID; i++)
                    c[i] = fmaf(A[i], c[i], xs[s] * wg[i]);
            }
        }
#pragma unroll
        for (int i = 0; i < HID; i++) P[i] *= a16[i];
    }

    const size_t base = ((size_t)b * NCH + ch) * HID;
#pragma unroll
    for (int i = 0; i < HID; i++) { d_P[base + i] = P[i]; d_c[base + i] = c[i]; }
}

// ---------------- fast branch pass 2: serial scan over chunks ----------------
__global__ void scan_kernel() {
    int q = blockIdx.x * blockDim.x + threadIdx.x;
    if (q >= BB * HID) return;
    int b = q / HID;
    int i = q % HID;
    float h = 0.0f;
#pragma unroll 4
    for (int ch = 0; ch < NCH; ch++) {
        size_t idx = ((size_t)b * NCH + ch) * HID + i;
        d_H0[idx] = h;
        h = fmaf(d_P[idx], h, d_c[idx]);
    }
}

// ---------------- fast branch pass 3: emit y ----------------
__global__ void __launch_bounds__(256) pass2_kernel(
    const float* __restrict__ x, const float* __restrict__ w_in,
    const float* __restrict__ w_out, float* __restrict__ y)
{
    int q = blockIdx.x * blockDim.x + threadIdx.x;
    if (q >= BB * NCH) return;
    int b = q / NCH;
    int ch = q % NCH;

    float win[HID], wo[HID], h[HID];
#pragma unroll
    for (int i = 0; i < HID; i++) {
        win[i] = w_in[i];
        wo[i]  = w_out[i];
        h[i]   = d_H0[((size_t)b * NCH + ch) * HID + i];
    }

    const int t0 = ch * CCH;
    const float* xb = x + (size_t)b * TT;
    float* yb = y + (size_t)b * TT;

#pragma unroll 1
    for (int blk = 0; blk < CCH / 16; blk++) {
        int t = t0 + blk * 16;
        int j = (t >> 4) - 1; if (j < 0) j = 0;
        const float4* ap = (const float4*)(d_As + ((size_t)b * FF + j) * HID);
        const float4* gp = (const float4*)(d_gs + ((size_t)b * FF + j) * HID);
        float4 Aa = ap[0], Ab = ap[1];
        float4 ga = gp[0], gb = gp[1];
        float A[HID] = {Aa.x, Aa.y, Aa.z, Aa.w, Ab.x, Ab.y, Ab.z, Ab.w};
        float g[HID] = {ga.x, ga.y, ga.z, ga.w, gb.x, gb.y, gb.z, gb.w};
        float wg[HID];
#pragma unroll
        for (int i = 0; i < HID; i++) wg[i] = win[i] * g[i];

        const float4* xv = (const float4*)(xb + t);
#pragma unroll
        for (int s4 = 0; s4 < 4; s4++) {
            float4 xq = xv[s4];
            float xs[4] = {xq.x, xq.y, xq.z, xq.w};
#pragma unroll
            for (int s = 0; s < 4; s++) {
#pragma unroll
                for (int i = 0; i < HID; i++)
                    h[i] = fmaf(A[i], h[i], xs[s] * wg[i]);
                float yv = 0.0f;
#pragma unroll
                for (int i = 0; i < HID; i++) yv = fmaf(h[i], wo[i], yv);
                yb[t + s4 * 4 + s] = yv;
            }
        }
    }
}

// ---------------- launch ----------------
extern "C" void kernel_launch(void* const* d_in, const int* in_sizes, int n_in,
                              void* d_out, int out_size) {
    const float* x    = (const float*)d_in[0];
    const float* w_in = (const float*)d_in[1];
    const float* w_out= (const float*)d_in[2];
    const float* w_ih = (const float*)d_in[3];
    const float* w_hh = (const float*)d_in[4];
    const float* b_ih = (const float*)d_in[5];
    const float* b_hh = (const float*)d_in[6];
    const float* w_sl = (const float*)d_in[7];
    const float* b_sl = (const float*)d_in[8];
    float* y = (float*)d_out;

    static int configured = 0;
    if (!configured) {
        cudaFuncSetAttribute(slow_kernel,
                             cudaFuncAttributeMaxDynamicSharedMemorySize,
                             SM_FLOATS * sizeof(float));
        configured = 1;
    }

    init_cpar_kernel<<<1, GH>>>(w_ih, b_ih, b_hh);
    slow_kernel<<<(FF + 1) / 2, SCOLS, SM_FLOATS * sizeof(float)>>>(x, w_hh, w_sl, b_sl);
    pass1_kernel<<<(BB * NCH) / 256, 256>>>(x, w_in);
    scan_kernel<<<(BB * HID + 255) / 256, 256>>>();
    pass2_kernel<<<(BB * NCH) / 256, 256>>>(x, w_in, w_out, y);
}

// round 3
// speedup vs baseline: 1.1558x; 1.1558x over previous
#include <cuda_runtime.h>
#include <math.h>

#define BB   128
#define TT   65536
#define DELTA 16
#define LS   32
#define HID  8
#define GH   64
#define ODIM 16
#define FF   4095            // (TT-LS)/DELTA + 1

#define CCH  256             // fast-branch chunk length (multiple of 16)
#define NCH  (TT/CCH)        // 256 chunks per batch row

#define SCOLS 256            // sequences per CTA in slow kernel (2 frames x 128 batch)

typedef unsigned long long u64;

// ---------------- device scratch (static, allocation-free) ----------------
__device__ float d_As[(size_t)BB * FF * HID];
__device__ float d_gs[(size_t)BB * FF * HID];
__device__ float d_P [BB * NCH * HID];
__device__ float d_c [BB * NCH * HID];
__device__ float d_H0[BB * NCH * HID];
__device__ float d_cpar[GH * 8];

// ---------------- f32x2 packed helpers ----------------
__device__ __forceinline__ u64 pack2(float lo, float hi) {
    u64 r; asm("mov.b64 %0, {%1, %2};" : "=l"(r) : "f"(lo), "f"(hi)); return r;
}
__device__ __forceinline__ void unpack2(u64 v, float& lo, float& hi) {
    asm("mov.b64 {%0, %1}, %2;" : "=f"(lo), "=f"(hi) : "l"(v));
}
__device__ __forceinline__ u64 ffma2(u64 a, u64 b, u64 c) {
    u64 d; asm("fma.rn.f32x2 %0, %1, %2, %3;" : "=l"(d) : "l"(a), "l"(b), "l"(c)); return d;
}

// ---------------- math helpers ----------------
__device__ __forceinline__ float sigf(float v) {
    return __fdividef(1.0f, 1.0f + __expf(-v));
}
__device__ __forceinline__ float tanh_f(float v) {
    v = fminf(fmaxf(v, -15.0f), 15.0f);
    float e = __expf(-2.0f * v);
    return __fdividef(1.0f - e, 1.0f + e);
}

// ---------------- init: pack per-j gate constants ----------------
__global__ void init_cpar_kernel(const float* __restrict__ w_ih,
                                 const float* __restrict__ b_ih,
                                 const float* __restrict__ b_hh) {
    int j = threadIdx.x;
    if (j < GH) {
        d_cpar[j*8+0] = w_ih[j];
        d_cpar[j*8+1] = w_ih[GH + j];
        d_cpar[j*8+2] = w_ih[2*GH + j];
        d_cpar[j*8+3] = b_ih[j]      + b_hh[j];
        d_cpar[j*8+4] = b_ih[GH + j] + b_hh[GH + j];
        d_cpar[j*8+5] = b_ih[2*GH + j];
        d_cpar[j*8+6] = b_hh[2*GH + j];
        d_cpar[j*8+7] = 0.0f;
    }
}

// ---------------- slow branch: GRU with packed f32x2 FMAs ----------------
// Smem layout (floats):
//   wrz  [64 j][64 k] float2 (wr,wz)         : 8192
//   wnn  [32 jp][64 k] float2 (wn_2p,wn_2p+1): 4096
//   h0, h1: [64 k][SCOLS]                    : 16384 each
//   cpar 512 | wsl 1024 | bsl 16
#define SM_WRZ  0
#define SM_WNN  8192
#define SM_H0   12288
#define SM_H1   (SM_H0 + 64*SCOLS)
#define SM_CPAR (SM_H1 + 64*SCOLS)
#define SM_WSL  (SM_CPAR + 512)
#define SM_BSL  (SM_WSL + ODIM*GH)
#define SM_FLOATS (SM_BSL + 16)

extern __shared__ float smem[];

__global__ void __launch_bounds__(SCOLS) slow_kernel(
    const float* __restrict__ x,
    const float* __restrict__ w_hh,
    const float* __restrict__ w_sl,
    const float* __restrict__ b_sl)
{
    const int tid = threadIdx.x;

    // interleave weights for packed FMA
    for (int i = tid; i < GH * GH; i += SCOLS) {
        int j = i >> 6, k = i & 63;
        ((float2*)(smem + SM_WRZ))[j * 64 + k] =
            make_float2(w_hh[j * GH + k], w_hh[(GH + j) * GH + k]);
    }
    for (int i = tid; i < (GH/2) * GH; i += SCOLS) {
        int p = i >> 6, k = i & 63;
        ((float2*)(smem + SM_WNN))[p * 64 + k] =
            make_float2(w_hh[(2*GH + 2*p) * GH + k], w_hh[(2*GH + 2*p + 1) * GH + k]);
    }
    for (int i = tid; i < GH * 8;    i += SCOLS) smem[SM_CPAR + i] = d_cpar[i];
    for (int i = tid; i < ODIM * GH; i += SCOLS) smem[SM_WSL + i] = w_sl[i];
    if (tid < ODIM) smem[SM_BSL + tid] = b_sl[tid];
    for (int k = 0; k < GH; k++) smem[SM_H0 + k * SCOLS + tid] = 0.0f;
    __syncthreads();

    const int b  = tid & 127;
    const int fi = tid >> 7;
    const int f  = blockIdx.x * 2 + fi;
    const bool active = (f < FF);

    const float* xp = x + (size_t)b * TT + (size_t)(active ? f : 0) * DELTA;

    float* hc = smem + SM_H0 + tid;
    float* hn = smem + SM_H1 + tid;
    const float* cpar = smem + SM_CPAR;

    float xt = active ? xp[0] : 0.0f;

#pragma unroll 1
    for (int t = 0; t < LS; t++) {
        float xnext = (active && t < LS - 1) ? xp[t + 1] : 0.0f;

#pragma unroll 1
        for (int jt = 0; jt < 4; jt++) {       // 16 j's per tile
            u64 arz[16], ann[8];
#pragma unroll
            for (int q = 0; q < 16; q++) arz[q] = 0ull;
#pragma unroll
            for (int q = 0; q < 8;  q++) ann[q] = 0ull;

            const float2* wrzp = (const float2*)(smem + SM_WRZ) + (size_t)(jt * 16) * 64;
            const float2* wnnp = (const float2*)(smem + SM_WNN) + (size_t)(jt * 8)  * 64;

#pragma unroll 1
            for (int kc = 0; kc < 8; kc++) {   // 8 k's per chunk
                u64 hd[8];
#pragma unroll
                for (int k = 0; k < 8; k++) {
                    float hv = hc[(kc * 8 + k) * SCOLS];
                    hd[k] = pack2(hv, hv);
                }
#pragma unroll
                for (int p = 0; p < 8; p++) {
                    const ulonglong2* w0 = (const ulonglong2*)(wrzp + (2*p    ) * 64 + kc * 8);
                    const ulonglong2* w1 = (const ulonglong2*)(wrzp + (2*p + 1) * 64 + kc * 8);
                    const ulonglong2* wn = (const ulonglong2*)(wnnp + p * 64 + kc * 8);
#pragma unroll
                    for (int k2 = 0; k2 < 4; k2++) {
                        ulonglong2 a = w0[k2];
                        ulonglong2 bb = w1[k2];
                        ulonglong2 cc = wn[k2];
                        arz[2*p]   = ffma2(a.x,  hd[2*k2],   arz[2*p]);
                        arz[2*p]   = ffma2(a.y,  hd[2*k2+1], arz[2*p]);
                        arz[2*p+1] = ffma2(bb.x, hd[2*k2],   arz[2*p+1]);
                        arz[2*p+1] = ffma2(bb.y, hd[2*k2+1], arz[2*p+1]);
                        ann[p]     = ffma2(cc.x, hd[2*k2],   ann[p]);
                        ann[p]     = ffma2(cc.y, hd[2*k2+1], ann[p]);
                    }
                }
            }

            // nonlinearities for this tile's 16 j's (8 pairs)
#pragma unroll
            for (int p = 0; p < 8; p++) {
                const int j = jt * 16 + 2 * p;
                float ar0, az0, ar1, az1, an0, an1;
                unpack2(arz[2*p],   ar0, az0);
                unpack2(arz[2*p+1], ar1, az1);
                unpack2(ann[p],     an0, an1);
                {
                    const float4 c0 = ((const float4*)(cpar + j * 8))[0];
                    const float4 c1 = ((const float4*)(cpar + j * 8))[1];
                    float hold = hc[j * SCOLS];
                    float r = sigf(fmaf(xt, c0.x, c0.w) + ar0);
                    float z = sigf(fmaf(xt, c0.y, c1.x) + az0);
                    float n = tanh_f(fmaf(xt, c0.z, c1.y) + r * (an0 + c1.z));
                    hn[j * SCOLS] = n + z * (hold - n);
                }
                {
                    const float4 c0 = ((const float4*)(cpar + (j+1) * 8))[0];
                    const float4 c1 = ((const float4*)(cpar + (j+1) * 8))[1];
                    float hold = hc[(j+1) * SCOLS];
                    float r = sigf(fmaf(xt, c0.x, c0.w) + ar1);
                    float z = sigf(fmaf(xt, c0.y, c1.x) + az1);
                    float n = tanh_f(fmaf(xt, c0.z, c1.y) + r * (an1 + c1.z));
                    hn[(j+1) * SCOLS] = n + z * (hold - n);
                }
            }
        }
        float* tmp = hc; hc = hn; hn = tmp;
        xt = xnext;
    }

    // epilogue: eps = w_sl @ h + b_sl
    if (active) {
        const float* wsl = smem + SM_WSL;
        const float* bsl = smem + SM_BSL;
        const size_t base = ((size_t)b * FF + f) * HID;
#pragma unroll 1
        for (int o = 0; o < HID; o++) {
            float a0 = bsl[o];
            float a1 = bsl[HID + o];
            const float4* w0 = (const float4*)(wsl + o * GH);
            const float4* w1 = (const float4*)(wsl + (HID + o) * GH);
#pragma unroll
            for (int k4 = 0; k4 < 16; k4++) {
                float h0v = hc[(k4*4 + 0) * SCOLS];
                float h1v = hc[(k4*4 + 1) * SCOLS];
                float h2v = hc[(k4*4 + 2) * SCOLS];
                float h3v = hc[(k4*4 + 3) * SCOLS];
                float4 v0 = w0[k4], v1 = w1[k4];
                a0 = fmaf(v0.x, h0v, a0); a0 = fmaf(v0.y, h1v, a0);
                a0 = fmaf(v0.z, h2v, a0); a0 = fmaf(v0.w, h3v, a0);
                a1 = fmaf(v1.x, h0v, a1); a1 = fmaf(v1.y, h1v, a1);
                a1 = fmaf(v1.z, h2v, a1); a1 = fmaf(v1.w, h3v, a1);
            }
            d_As[base + o] = sigf(a0);
            d_gs[base + o] = a1;
        }
    }
}

// ---------------- fast branch pass 1: per-chunk (P, c) ----------------
__global__ void __launch_bounds__(256) pass1_kernel(
    const float* __restrict__ x, const float* __restrict__ w_in)
{
    int q = blockIdx.x * blockDim.x + threadIdx.x;
    if (q >= BB * NCH) return;
    int b = q / NCH;
    int ch = q % NCH;

    float win[HID];
#pragma unroll
    for (int i = 0; i < HID; i++) win[i] = w_in[i];

    float P[HID], c[HID];
#pragma unroll
    for (int i = 0; i < HID; i++) { P[i] = 1.0f; c[i] = 0.0f; }

    const int t0 = ch * CCH;
    const float* xb = x + (size_t)b * TT;

#pragma unroll 1
    for (int blk = 0; blk < CCH / 16; blk++) {
        int t = t0 + blk * 16;
        int j = (t >> 4) - 1; if (j < 0) j = 0;
        const float4* ap = (const float4*)(d_As + ((size_t)b * FF + j) * HID);
        const float4* gp = (const float4*)(d_gs + ((size_t)b * FF + j) * HID);
        float4 Aa = ap[0], Ab = ap[1];
        float4 ga = gp[0], gb = gp[1];
        float A[HID] = {Aa.x, Aa.y, Aa.z, Aa.w, Ab.x, Ab.y, Ab.z, Ab.w};
        float g[HID] = {ga.x, ga.y, ga.z, ga.w, gb.x, gb.y, gb.z, gb.w};
        float wg[HID], a16[HID];
#pragma unroll
        for (int i = 0; i < HID; i++) {
            wg[i] = win[i] * g[i];
            float a2 = A[i] * A[i];
            float a4 = a2 * a2;
            float a8 = a4 * a4;
            a16[i] = a8 * a8;
        }
        const float4* xv = (const float4*)(xb + t);
#pragma unroll
        for (int s4 = 0; s4 < 4; s4++) {
            float4 xq = xv[s4];
            float xs[4] = {xq.x, xq.y, xq.z, xq.w};
#pragma unroll
            for (int s = 0; s < 4; s++) {
#pragma unroll
                for (int i = 0; i < HID; i++)
                    c[i] = fmaf(A[i], c[i], xs[s] * wg[i]);
            }
        }
#pragma unroll
        for (int i = 0; i < HID; i++) P[i] *= a16[i];
    }

    const size_t base = ((size_t)b * NCH + ch) * HID;
#pragma unroll
    for (int i = 0; i < HID; i++) { d_P[base + i] = P[i]; d_c[base + i] = c[i]; }
}

// ---------------- fast branch pass 2: warp-parallel scan over chunks ----------
// 1024 (b,i) chains; one warp per chain; lane owns 8 consecutive chunks.
__global__ void __launch_bounds__(256) scan_kernel() {
    int gw   = (blockIdx.x * blockDim.x + threadIdx.x) >> 5;
    int lane = threadIdx.x & 31;
    int b = gw >> 3;
    int i = gw & 7;

    float P[8], c[8];
#pragma unroll
    for (int s = 0; s < 8; s++) {
        size_t idx = ((size_t)b * NCH + (lane * 8 + s)) * HID + i;
        P[s] = d_P[idx];
        c[s] = d_c[idx];
    }
    float Pt = 1.0f, ct = 0.0f;
#pragma unroll
    for (int s = 0; s < 8; s++) { ct = fmaf(P[s], ct, c[s]); Pt *= P[s]; }

    // inclusive Hillis-Steele scan with affine composition
#pragma unroll
    for (int off = 1; off < 32; off <<= 1) {
        float Pp = __shfl_up_sync(0xffffffffu, Pt, off);
        float cp = __shfl_up_sync(0xffffffffu, ct, off);
        if (lane >= off) { ct = fmaf(Pt, cp, ct); Pt *= Pp; }
    }
    // exclusive offset (h starts at 0, so h at lane start = previous lane's ct)
    float h = __shfl_up_sync(0xffffffffu, ct, 1);
    if (lane == 0) h = 0.0f;

#pragma unroll
    for (int s = 0; s < 8; s++) {
        size_t idx = ((size_t)b * NCH + (lane * 8 + s)) * HID + i;
        d_H0[idx] = h;
        h = fmaf(P[s], h, c[s]);
    }
}

// ---------------- fast branch pass 3: emit y ----------------
__global__ void __launch_bounds__(256) pass2_kernel(
    const float* __restrict__ x, const float* __restrict__ w_in,
    const float* __restrict__ w_out, float* __restrict__ y)
{
    int q = blockIdx.x * blockDim.x + threadIdx.x;
    if (q >= BB * NCH) return;
    int b = q / NCH;
    int ch = q % NCH;

    float win[HID], wo[HID], h[HID];
#pragma unroll
    for (int i = 0; i < HID; i++) {
        win[i] = w_in[i];
        wo[i]  = w_out[i];
        h[i]   = d_H0[((size_t)b * NCH + ch) * HID + i];
    }

    const int t0 = ch * CCH;
    const float* xb = x + (size_t)b * TT;
    float* yb = y + (size_t)b * TT;

#pragma unroll 1
    for (int blk = 0; blk < CCH / 16; blk++) {
        int t = t0 + blk * 16;
        int j = (t >> 4) - 1; if (j < 0) j = 0;
        const float4* ap = (const float4*)(d_As + ((size_t)b * FF + j) * HID);
        const float4* gp = (const float4*)(d_gs + ((size_t)b * FF + j) * HID);
        float4 Aa = ap[0], Ab = ap[1];
        float4 ga = gp[0], gb = gp[1];
        float A[HID] = {Aa.x, Aa.y, Aa.z, Aa.w, Ab.x, Ab.y, Ab.z, Ab.w};
        float g[HID] = {ga.x, ga.y, ga.z, ga.w, gb.x, gb.y, gb.z, gb.w};
        float wg[HID];
#pragma unroll
        for (int i = 0; i < HID; i++) wg[i] = win[i] * g[i];

        const float4* xv = (const float4*)(xb + t);
#pragma unroll
        for (int s4 = 0; s4 < 4; s4++) {
            float4 xq = xv[s4];
            float xs[4] = {xq.x, xq.y, xq.z, xq.w};
#pragma unroll
            for (int s = 0; s < 4; s++) {
#pragma unroll
                for (int i = 0; i < HID; i++)
                    h[i] = fmaf(A[i], h[i], xs[s] * wg[i]);
                float yv = 0.0f;
#pragma unroll
                for (int i = 0; i < HID; i++) yv = fmaf(h[i], wo[i], yv);
                yb[t + s4 * 4 + s] = yv;
            }
        }
    }
}

// ---------------- launch ----------------
extern "C" void kernel_launch(void* const* d_in, const int* in_sizes, int n_in,
                              void* d_out, int out_size) {
    const float* x    = (const float*)d_in[0];
    const float* w_in = (const float*)d_in[1];
    const float* w_out= (const float*)d_in[2];
    const float* w_ih = (const float*)d_in[3];
    const float* w_hh = (const float*)d_in[4];
    const float* b_ih = (const float*)d_in[5];
    const float* b_hh = (const float*)d_in[6];
    const float* w_sl = (const float*)d_in[7];
    const float* b_sl = (const float*)d_in[8];
    float* y = (float*)d_out;

    static int configured = 0;
    if (!configured) {
        cudaFuncSetAttribute(slow_kernel,
                             cudaFuncAttributeMaxDynamicSharedMemorySize,
                             SM_FLOATS * sizeof(float));
        configured = 1;
    }

    init_cpar_kernel<<<1, GH>>>(w_ih, b_ih, b_hh);
    slow_kernel<<<(FF + 1) / 2, SCOLS, SM_FLOATS * sizeof(float)>>>(x, w_hh, w_sl, b_sl);
    pass1_kernel<<<(BB * NCH) / 256, 256>>>(x, w_in);
    scan_kernel<<<(BB * HID * 32) / 256, 256>>>();
    pass2_kernel<<<(BB * NCH) / 256, 256>>>(x, w_in, w_out, y);
}

// round 4
// speedup vs baseline: 1.1561x; 1.0002x over previous
#include <cuda_runtime.h>
#include <math.h>

#define BB   128
#define TT   65536
#define DELTA 16
#define LS   32
#define HID  8
#define GH   64
#define ODIM 16
#define FF   4095            // (TT-LS)/DELTA + 1

#define CCH  256             // fast-branch chunk length (multiple of 16)
#define NCH  (TT/CCH)        // 256 chunks per batch row

#define SCOLS 256            // sequences per CTA in slow kernel (2 frames x 128 batch)

typedef unsigned long long u64;

// ---------------- device scratch (static, allocation-free) ----------------
__device__ float d_As[(size_t)BB * FF * HID];
__device__ float d_gs[(size_t)BB * FF * HID];
__device__ float d_P [BB * NCH * HID];
__device__ float d_c [BB * NCH * HID];
__device__ float d_H0[BB * NCH * HID];
__device__ float d_cpar[GH * 8];

// ---------------- f32x2 packed helpers ----------------
__device__ __forceinline__ u64 pack2(float lo, float hi) {
    u64 r; asm("mov.b64 %0, {%1, %2};" : "=l"(r) : "f"(lo), "f"(hi)); return r;
}
__device__ __forceinline__ void unpack2(u64 v, float& lo, float& hi) {
    asm("mov.b64 {%0, %1}, %2;" : "=f"(lo), "=f"(hi) : "l"(v));
}
__device__ __forceinline__ u64 ffma2(u64 a, u64 b, u64 c) {
    u64 d; asm("fma.rn.f32x2 %0, %1, %2, %3;" : "=l"(d) : "l"(a), "l"(b), "l"(c)); return d;
}

// ---------------- math helpers ----------------
__device__ __forceinline__ float sigf(float v) {
    return __fdividef(1.0f, 1.0f + __expf(-v));
}
__device__ __forceinline__ float tanh_f(float v) {
    v = fminf(fmaxf(v, -15.0f), 15.0f);
    float e = __expf(-2.0f * v);
    return __fdividef(1.0f - e, 1.0f + e);
}

// ---------------- init: pack per-j gate constants ----------------
__global__ void init_cpar_kernel(const float* __restrict__ w_ih,
                                 const float* __restrict__ b_ih,
                                 const float* __restrict__ b_hh) {
    int j = threadIdx.x;
    if (j < GH) {
        d_cpar[j*8+0] = w_ih[j];
        d_cpar[j*8+1] = w_ih[GH + j];
        d_cpar[j*8+2] = w_ih[2*GH + j];
        d_cpar[j*8+3] = b_ih[j]      + b_hh[j];
        d_cpar[j*8+4] = b_ih[GH + j] + b_hh[GH + j];
        d_cpar[j*8+5] = b_ih[2*GH + j];
        d_cpar[j*8+6] = b_hh[2*GH + j];
        d_cpar[j*8+7] = 0.0f;
    }
}

// ---------------- slow branch: GRU with packed f32x2 FMAs ----------------
// Smem layout (floats):
//   wrz  [64 j][64 k] float2 (wr,wz)         : 8192
//   wnn  [32 jp][64 k] float2 (wn_2p,wn_2p+1): 4096
//   h0, h1: [64 k][SCOLS]                    : 16384 each
//   cpar 512 | wsl 1024 | bsl 16
#define SM_WRZ  0
#define SM_WNN  8192
#define SM_H0   12288
#define SM_H1   (SM_H0 + 64*SCOLS)
#define SM_CPAR (SM_H1 + 64*SCOLS)
#define SM_WSL  (SM_CPAR + 512)
#define SM_BSL  (SM_WSL + ODIM*GH)
#define SM_FLOATS (SM_BSL + 16)

extern __shared__ float smem[];

__global__ void __launch_bounds__(SCOLS) slow_kernel(
    const float* __restrict__ x,
    const float* __restrict__ w_hh,
    const float* __restrict__ w_sl,
    const float* __restrict__ b_sl)
{
    const int tid = threadIdx.x;

    // interleave weights for packed FMA
    for (int i = tid; i < GH * GH; i += SCOLS) {
        int j = i >> 6, k = i & 63;
        ((float2*)(smem + SM_WRZ))[j * 64 + k] =
            make_float2(w_hh[j * GH + k], w_hh[(GH + j) * GH + k]);
    }
    for (int i = tid; i < (GH/2) * GH; i += SCOLS) {
        int p = i >> 6, k = i & 63;
        ((float2*)(smem + SM_WNN))[p * 64 + k] =
            make_float2(w_hh[(2*GH + 2*p) * GH + k], w_hh[(2*GH + 2*p + 1) * GH + k]);
    }
    for (int i = tid; i < GH * 8;    i += SCOLS) smem[SM_CPAR + i] = d_cpar[i];
    for (int i = tid; i < ODIM * GH; i += SCOLS) smem[SM_WSL + i] = w_sl[i];
    if (tid < ODIM) smem[SM_BSL + tid] = b_sl[tid];
    for (int k = 0; k < GH; k++) smem[SM_H0 + k * SCOLS + tid] = 0.0f;
    __syncthreads();

    const int b  = tid & 127;
    const int fi = tid >> 7;
    const int f  = blockIdx.x * 2 + fi;
    const bool active = (f < FF);

    const float* xp = x + (size_t)b * TT + (size_t)(active ? f : 0) * DELTA;

    float* hc = smem + SM_H0 + tid;
    float* hn = smem + SM_H1 + tid;
    const float* cpar = smem + SM_CPAR;

    float xt = active ? xp[0] : 0.0f;

#pragma unroll 1
    for (int t = 0; t < LS; t++) {
        float xnext = (active && t < LS - 1) ? xp[t + 1] : 0.0f;

#pragma unroll 1
        for (int jt = 0; jt < 4; jt++) {       // 16 j's per tile
            u64 arz[16], ann[8];
#pragma unroll
            for (int q = 0; q < 16; q++) arz[q] = 0ull;
#pragma unroll
            for (int q = 0; q < 8;  q++) ann[q] = 0ull;

            const float2* wrzp = (const float2*)(smem + SM_WRZ) + (size_t)(jt * 16) * 64;
            const float2* wnnp = (const float2*)(smem + SM_WNN) + (size_t)(jt * 8)  * 64;

#pragma unroll 1
            for (int kc = 0; kc < 8; kc++) {   // 8 k's per chunk
                u64 hd[8];
#pragma unroll
                for (int k = 0; k < 8; k++) {
                    float hv = hc[(kc * 8 + k) * SCOLS];
                    hd[k] = pack2(hv, hv);
                }
#pragma unroll
                for (int p = 0; p < 8; p++) {
                    const ulonglong2* w0 = (const ulonglong2*)(wrzp + (2*p    ) * 64 + kc * 8);
                    const ulonglong2* w1 = (const ulonglong2*)(wrzp + (2*p + 1) * 64 + kc * 8);
                    const ulonglong2* wn = (const ulonglong2*)(wnnp + p * 64 + kc * 8);
#pragma unroll
                    for (int k2 = 0; k2 < 4; k2++) {
                        ulonglong2 a = w0[k2];
                        ulonglong2 bb = w1[k2];
                        ulonglong2 cc = wn[k2];
                        arz[2*p]   = ffma2(a.x,  hd[2*k2],   arz[2*p]);
                        arz[2*p]   = ffma2(a.y,  hd[2*k2+1], arz[2*p]);
                        arz[2*p+1] = ffma2(bb.x, hd[2*k2],   arz[2*p+1]);
                        arz[2*p+1] = ffma2(bb.y, hd[2*k2+1], arz[2*p+1]);
                        ann[p]     = ffma2(cc.x, hd[2*k2],   ann[p]);
                        ann[p]     = ffma2(cc.y, hd[2*k2+1], ann[p]);
                    }
                }
            }

            // nonlinearities for this tile's 16 j's (8 pairs)
#pragma unroll
            for (int p = 0; p < 8; p++) {
                const int j = jt * 16 + 2 * p;
                float ar0, az0, ar1, az1, an0, an1;
                unpack2(arz[2*p],   ar0, az0);
                unpack2(arz[2*p+1], ar1, az1);
                unpack2(ann[p],     an0, an1);
                {
                    const float4 c0 = ((const float4*)(cpar + j * 8))[0];
                    const float4 c1 = ((const float4*)(cpar + j * 8))[1];
                    float hold = hc[j * SCOLS];
                    float r = sigf(fmaf(xt, c0.x, c0.w) + ar0);
                    float z = sigf(fmaf(xt, c0.y, c1.x) + az0);
                    float n = tanh_f(fmaf(xt, c0.z, c1.y) + r * (an0 + c1.z));
                    hn[j * SCOLS] = n + z * (hold - n);
                }
                {
                    const float4 c0 = ((const float4*)(cpar + (j+1) * 8))[0];
                    const float4 c1 = ((const float4*)(cpar + (j+1) * 8))[1];
                    float hold = hc[(j+1) * SCOLS];
                    float r = sigf(fmaf(xt, c0.x, c0.w) + ar1);
                    float z = sigf(fmaf(xt, c0.y, c1.x) + az1);
                    float n = tanh_f(fmaf(xt, c0.z, c1.y) + r * (an1 + c1.z));
                    hn[(j+1) * SCOLS] = n + z * (hold - n);
                }
            }
        }
        float* tmp = hc; hc = hn; hn = tmp;
        xt = xnext;
    }

    // epilogue: eps = w_sl @ h + b_sl
    if (active) {
        const float* wsl = smem + SM_WSL;
        const float* bsl = smem + SM_BSL;
        const size_t base = ((size_t)b * FF + f) * HID;
#pragma unroll 1
        for (int o = 0; o < HID; o++) {
            float a0 = bsl[o];
            float a1 = bsl[HID + o];
            const float4* w0 = (const float4*)(wsl + o * GH);
            const float4* w1 = (const float4*)(wsl + (HID + o) * GH);
#pragma unroll
            for (int k4 = 0; k4 < 16; k4++) {
                float h0v = hc[(k4*4 + 0) * SCOLS];
                float h1v = hc[(k4*4 + 1) * SCOLS];
                float h2v = hc[(k4*4 + 2) * SCOLS];
                float h3v = hc[(k4*4 + 3) * SCOLS];
                float4 v0 = w0[k4], v1 = w1[k4];
                a0 = fmaf(v0.x, h0v, a0); a0 = fmaf(v0.y, h1v, a0);
                a0 = fmaf(v0.z, h2v, a0); a0 = fmaf(v0.w, h3v, a0);
                a1 = fmaf(v1.x, h0v, a1); a1 = fmaf(v1.y, h1v, a1);
                a1 = fmaf(v1.z, h2v, a1); a1 = fmaf(v1.w, h3v, a1);
            }
            d_As[base + o] = sigf(a0);
            d_gs[base + o] = a1;
        }
    }
}

// ---------------- fast branch pass 1: per-chunk (P, c) ----------------
__global__ void __launch_bounds__(256) pass1_kernel(
    const float* __restrict__ x, const float* __restrict__ w_in)
{
    int q = blockIdx.x * blockDim.x + threadIdx.x;
    if (q >= BB * NCH) return;
    int b = q / NCH;
    int ch = q % NCH;

    float win[HID];
#pragma unroll
    for (int i = 0; i < HID; i++) win[i] = w_in[i];

    float P[HID], c[HID];
#pragma unroll
    for (int i = 0; i < HID; i++) { P[i] = 1.0f; c[i] = 0.0f; }

    const int t0 = ch * CCH;
    const float* xb = x + (size_t)b * TT;

#pragma unroll 1
    for (int blk = 0; blk < CCH / 16; blk++) {
        int t = t0 + blk * 16;
        int j = (t >> 4) - 1; if (j < 0) j = 0;
        const float4* ap = (const float4*)(d_As + ((size_t)b * FF + j) * HID);
        const float4* gp = (const float4*)(d_gs + ((size_t)b * FF + j) * HID);
        float4 Aa = ap[0], Ab = ap[1];
        float4 ga = gp[0], gb = gp[1];
        float A[HID] = {Aa.x, Aa.y, Aa.z, Aa.w, Ab.x, Ab.y, Ab.z, Ab.w};
        float g[HID] = {ga.x, ga.y, ga.z, ga.w, gb.x, gb.y, gb.z, gb.w};
        float wg[HID], a16[HID];
#pragma unroll
        for (int i = 0; i < HID; i++) {
            wg[i] = win[i] * g[i];
            float a2 = A[i] * A[i];
            float a4 = a2 * a2;
            float a8 = a4 * a4;
            a16[i] = a8 * a8;
        }
        const float4* xv = (const float4*)(xb + t);
#pragma unroll
        for (int s4 = 0; s4 < 4; s4++) {
            float4 xq = xv[s4];
            float xs[4] = {xq.x, xq.y, xq.z, xq.w};
#pragma unroll
            for (int s = 0; s < 4; s++) {
#pragma unroll
                for (int i = 0; i < HID; i++)
                    c[i] = fmaf(A[i], c[i], xs[s] * wg[i]);
            }
        }
#pragma unroll
        for (int i = 0; i < HID; i++) P[i] *= a16[i];
    }

    const size_t base = ((size_t)b * NCH + ch) * HID;
#pragma unroll
    for (int i = 0; i < HID; i++) { d_P[base + i] = P[i]; d_c[base + i] = c[i]; }
}

// ---------------- fast branch pass 2: warp-parallel scan over chunks ----------
// 1024 (b,i) chains; one warp per chain; lane owns 8 consecutive chunks.
__global__ void __launch_bounds__(256) scan_kernel() {
    int gw   = (blockIdx.x * blockDim.x + threadIdx.x) >> 5;
    int lane = threadIdx.x & 31;
    int b = gw >> 3;
    int i = gw & 7;

    float P[8], c[8];
#pragma unroll
    for (int s = 0; s < 8; s++) {
        size_t idx = ((size_t)b * NCH + (lane * 8 + s)) * HID + i;
        P[s] = d_P[idx];
        c[s] = d_c[idx];
    }
    float Pt = 1.0f, ct = 0.0f;
#pragma unroll
    for (int s = 0; s < 8; s++) { ct = fmaf(P[s], ct, c[s]); Pt *= P[s]; }

    // inclusive Hillis-Steele scan with affine composition
#pragma unroll
    for (int off = 1; off < 32; off <<= 1) {
        float Pp = __shfl_up_sync(0xffffffffu, Pt, off);
        float cp = __shfl_up_sync(0xffffffffu, ct, off);
        if (lane >= off) { ct = fmaf(Pt, cp, ct); Pt *= Pp; }
    }
    // exclusive offset (h starts at 0, so h at lane start = previous lane's ct)
    float h = __shfl_up_sync(0xffffffffu, ct, 1);
    if (lane == 0) h = 0.0f;

#pragma unroll
    for (int s = 0; s < 8; s++) {
        size_t idx = ((size_t)b * NCH + (lane * 8 + s)) * HID + i;
        d_H0[idx] = h;
        h = fmaf(P[s], h, c[s]);
    }
}

// ---------------- fast branch pass 3: emit y ----------------
__global__ void __launch_bounds__(256) pass2_kernel(
    const float* __restrict__ x, const float* __restrict__ w_in,
    const float* __restrict__ w_out, float* __restrict__ y)
{
    int q = blockIdx.x * blockDim.x + threadIdx.x;
    if (q >= BB * NCH) return;
    int b = q / NCH;
    int ch = q % NCH;

    float win[HID], wo[HID], h[HID];
#pragma unroll
    for (int i = 0; i < HID; i++) {
        win[i] = w_in[i];
        wo[i]  = w_out[i];
        h[i]   = d_H0[((size_t)b * NCH + ch) * HID + i];
    }

    const int t0 = ch * CCH;
    const float* xb = x + (size_t)b * TT;
    float* yb = y + (size_t)b * TT;

#pragma unroll 1
    for (int blk = 0; blk < CCH / 16; blk++) {
        int t = t0 + blk * 16;
        int j = (t >> 4) - 1; if (j < 0) j = 0;
        const float4* ap = (const float4*)(d_As + ((size_t)b * FF + j) * HID);
        const float4* gp = (const float4*)(d_gs + ((size_t)b * FF + j) * HID);
        float4 Aa = ap[0], Ab = ap[1];
        float4 ga = gp[0], gb = gp[1];
        float A[HID] = {Aa.x, Aa.y, Aa.z, Aa.w, Ab.x, Ab.y, Ab.z, Ab.w};
        float g[HID] = {ga.x, ga.y, ga.z, ga.w, gb.x, gb.y, gb.z, gb.w};
        float wg[HID];
#pragma unroll
        for (int i = 0; i < HID; i++) wg[i] = win[i] * g[i];

        const float4* xv = (const float4*)(xb + t);
#pragma unroll
        for (int s4 = 0; s4 < 4; s4++) {
            float4 xq = xv[s4];
            float xs[4] = {xq.x, xq.y, xq.z, xq.w};
#pragma unroll
            for (int s = 0; s < 4; s++) {
#pragma unroll
                for (int i = 0; i < HID; i++)
                    h[i] = fmaf(A[i], h[i], xs[s] * wg[i]);
                float yv = 0.0f;
#pragma unroll
                for (int i = 0; i < HID; i++) yv = fmaf(h[i], wo[i], yv);
                yb[t + s4 * 4 + s] = yv;
            }
        }
    }
}

// ---------------- launch ----------------
extern "C" void kernel_launch(void* const* d_in, const int* in_sizes, int n_in,
                              void* d_out, int out_size) {
    const float* x    = (const float*)d_in[0];
    const float* w_in = (const float*)d_in[1];
    const float* w_out= (const float*)d_in[2];
    const float* w_ih = (const float*)d_in[3];
    const float* w_hh = (const float*)d_in[4];
    const float* b_ih = (const float*)d_in[5];
    const float* b_hh = (const float*)d_in[6];
    const float* w_sl = (const float*)d_in[7];
    const float* b_sl = (const float*)d_in[8];
    float* y = (float*)d_out;

    static int configured = 0;
    if (!configured) {
        cudaFuncSetAttribute(slow_kernel,
                             cudaFuncAttributeMaxDynamicSharedMemorySize,
                             SM_FLOATS * sizeof(float));
        configured = 1;
    }

    init_cpar_kernel<<<1, GH>>>(w_ih, b_ih, b_hh);
    slow_kernel<<<(FF + 1) / 2, SCOLS, SM_FLOATS * sizeof(float)>>>(x, w_hh, w_sl, b_sl);
    pass1_kernel<<<(BB * NCH) / 256, 256>>>(x, w_in);
    scan_kernel<<<(BB * HID * 32) / 256, 256>>>();
    pass2_kernel<<<(BB * NCH) / 256, 256>>>(x, w_in, w_out, y);
}

// round 6
// speedup vs baseline: 2.0351x; 1.7603x over previous
#include <cuda_runtime.h>
#include <cuda_bf16.h>
#include <mma.h>
#include <math.h>
#include <stdint.h>

using namespace nvcuda;

#define BB   128
#define TT   65536
#define DELTA 16
#define LS   32
#define HID  8
#define GH   64
#define ODIM 16
#define FF   4095
#define CCH  256
#define NCH  (TT/CCH)

typedef unsigned int u32;

// ---------------- device scratch ----------------
__device__ float d_As[(size_t)BB * FF * HID];
__device__ float d_gs[(size_t)BB * FF * HID];
__device__ float d_P [BB * NCH * HID];
__device__ float d_c [BB * NCH * HID];
__device__ float d_H0[BB * NCH * HID];
__device__ float d_cpar[GH * 8];

__device__ __forceinline__ float sigf(float v) {
    return __fdividef(1.0f, 1.0f + __expf(-v));
}
__device__ __forceinline__ float tanh_f(float v) {
    v = fminf(fmaxf(v, -15.0f), 15.0f);
    float e = __expf(-2.0f * v);
    return __fdividef(1.0f - e, 1.0f + e);
}

__global__ void init_cpar_kernel(const float* __restrict__ w_ih,
                                 const float* __restrict__ b_ih,
                                 const float* __restrict__ b_hh) {
    int j = threadIdx.x;
    if (j < GH) {
        d_cpar[j*8+0] = w_ih[j];
        d_cpar[j*8+1] = w_ih[GH + j];
        d_cpar[j*8+2] = w_ih[2*GH + j];
        d_cpar[j*8+3] = b_ih[j]      + b_hh[j];
        d_cpar[j*8+4] = b_ih[GH + j] + b_hh[GH + j];
        d_cpar[j*8+5] = b_ih[2*GH + j];
        d_cpar[j*8+6] = b_hh[2*GH + j];
        d_cpar[j*8+7] = 0.0f;
    }
}

// ---------------- smem layout (bytes) ----------------
// W padded [192][72] bf16 hi/lo; H padded [256][72] bf16 hi/lo;
// xs [256][33] f32; scratch 8 warps x 3 kinds x [16][36] f32; cpar; wsl; bsl
#define LDW   72
#define LDH   72
#define LDS_X 33
#define LDSC  36
#define SM_WHI  0
#define SM_WLO  (SM_WHI + 192*LDW*2)         // 27648
#define SM_HHI  (SM_WLO + 192*LDW*2)         // 55296
#define SM_HLO  (SM_HHI + 256*LDH*2)         // 92160
#define SM_XS   (SM_HLO + 256*LDH*2)         // 129024
#define SM_SCR  (SM_XS + 256*LDS_X*4)        // 162816
#define SCR_WARP (3*16*LDSC)                 // floats per warp
#define SM_CPAR (SM_SCR + 8*SCR_WARP*4)      // 218112
#define SM_WSL  (SM_CPAR + GH*8*4)           // 220160
#define SM_BSL  (SM_WSL + ODIM*GH*4)         // 224256
#define SM_BYTES (SM_BSL + 64)               // 224320

// grid = 2048 CTAs, 256 threads. CTA covers frames {2c, 2c+1} x 128 batch rows.
// Warp w owns sequence columns [32w, 32w+32) — fully independent GRUs.
__global__ void __launch_bounds__(256, 1) slow_wmma_kernel(
    const float* __restrict__ x,
    const float* __restrict__ w_hh,
    const float* __restrict__ w_sl,
    const float* __restrict__ b_sl)
{
    extern __shared__ char sm[];
    const int tid  = threadIdx.x;
    const int wid  = tid >> 5;
    const int lane = tid & 31;
    const int f0   = blockIdx.x * 2;
    const int cb   = wid * 32;            // warp's first column

    __nv_bfloat16* WHI = (__nv_bfloat16*)(sm + SM_WHI);
    __nv_bfloat16* WLO = (__nv_bfloat16*)(sm + SM_WLO);
    __nv_bfloat16* HHI = (__nv_bfloat16*)(sm + SM_HHI);
    __nv_bfloat16* HLO = (__nv_bfloat16*)(sm + SM_HLO);
    float* xs     = (float*)(sm + SM_XS);
    float* scr    = (float*)(sm + SM_SCR) + wid * SCR_WARP;
    float* cparsm = (float*)(sm + SM_CPAR);
    float* wslsm  = (float*)(sm + SM_WSL);
    float* bslsm  = (float*)(sm + SM_BSL);

    // ---- prologue ----
    for (int i = tid; i < 192 * GH; i += 256) {
        int g = i >> 6, k = i & 63;
        float v = w_hh[i];
        __nv_bfloat16 hi = __float2bfloat16(v);
        __nv_bfloat16 lo = __float2bfloat16(v - __bfloat162float(hi));
        WHI[g * LDW + k] = hi;
        WLO[g * LDW + k] = lo;
    }
    // zero H (hi+lo contiguous region)
    for (int i = tid; i < (256 * LDH * 2 * 2) / 4; i += 256)
        ((u32*)(sm + SM_HHI))[i] = 0u;
    // stage x: col c needs x[b*TT + f*16 + t], t=0..31
    {
        int c = tid;
        int b = c & 127;
        int f = f0 + (c >> 7); if (f > FF - 1) f = FF - 1;
        const float* xp = x + (size_t)b * TT + (size_t)f * DELTA;
#pragma unroll
        for (int t = 0; t < LS; t++) xs[c * LDS_X + t] = xp[t];
    }
    for (int i = tid; i < GH * 8;    i += 256) cparsm[i] = d_cpar[i];
    for (int i = tid; i < ODIM * GH; i += 256) wslsm[i]  = w_sl[i];
    if (tid < ODIM) bslsm[tid] = b_sl[tid];
    __syncthreads();

    // per-lane epilogue constants
    const int g8 = lane >> 3;               // column group 0..3
    const int jr = (lane & 7) * 2;          // even row in 0..14

    // ---- 32 GRU steps ----
#pragma unroll 1
    for (int t = 0; t < LS; t++) {
        // load B fragments (H hi/lo) for this warp's 32 columns
        wmma::fragment<wmma::matrix_b, 16,16,16, __nv_bfloat16, wmma::col_major> bHI[4][2], bLO[4][2];
#pragma unroll
        for (int kt = 0; kt < 4; kt++)
#pragma unroll
            for (int nt = 0; nt < 2; nt++) {
                wmma::load_matrix_sync(bHI[kt][nt], HHI + (size_t)(cb + nt*16) * LDH + kt*16, LDH);
                wmma::load_matrix_sync(bLO[kt][nt], HLO + (size_t)(cb + nt*16) * LDH + kt*16, LDH);
            }

#pragma unroll 1
        for (int mg = 0; mg < 4; mg++) {
            wmma::fragment<wmma::accumulator, 16,16,16, float> acc[3][2];
#pragma unroll
            for (int kind = 0; kind < 3; kind++)
#pragma unroll
                for (int nt = 0; nt < 2; nt++)
                    wmma::fill_fragment(acc[kind][nt], 0.0f);

#pragma unroll
            for (int kind = 0; kind < 3; kind++) {
                const int mi = kind * 4 + mg;
#pragma unroll
                for (int kt = 0; kt < 4; kt++) {
                    wmma::fragment<wmma::matrix_a, 16,16,16, __nv_bfloat16, wmma::row_major> aHI, aLO;
                    wmma::load_matrix_sync(aHI, WHI + (size_t)(mi*16) * LDW + kt*16, LDW);
                    wmma::load_matrix_sync(aLO, WLO + (size_t)(mi*16) * LDW + kt*16, LDW);
#pragma unroll
                    for (int nt = 0; nt < 2; nt++) {
                        wmma::mma_sync(acc[kind][nt], aHI, bHI[kt][nt], acc[kind][nt]);
                        wmma::mma_sync(acc[kind][nt], aHI, bLO[kt][nt], acc[kind][nt]);
                        wmma::mma_sync(acc[kind][nt], aLO, bHI[kt][nt], acc[kind][nt]);
                    }
                }
            }
#pragma unroll
            for (int kind = 0; kind < 3; kind++)
#pragma unroll
                for (int nt = 0; nt < 2; nt++)
                    wmma::store_matrix_sync(scr + kind*16*LDSC + nt*16, acc[kind][nt], LDSC, wmma::mem_row_major);
            __syncwarp();

            // nonlinearities: lane handles rows j, j+1 for 8 columns
            const int j = mg * 16 + jr;
            const float* cp0 = cparsm + j * 8;
            const float* cp1 = cparsm + (j + 1) * 8;
            const float cwr0 = cp0[0], cwz0 = cp0[1], cwn0 = cp0[2], cbr0 = cp0[3],
                        cbz0 = cp0[4], cbi0 = cp0[5], cbh0 = cp0[6];
            const float cwr1 = cp1[0], cwz1 = cp1[1], cwn1 = cp1[2], cbr1 = cp1[3],
                        cbz1 = cp1[4], cbi1 = cp1[5], cbh1 = cp1[6];
#pragma unroll
            for (int i = 0; i < 8; i++) {
                const int cl = g8 * 8 + i;
                const int c  = cb + cl;
                const float xt = xs[c * LDS_X + t];
                float gr0 = scr[0*16*LDSC + jr*LDSC + cl];
                float gz0 = scr[1*16*LDSC + jr*LDSC + cl];
                float gn0 = scr[2*16*LDSC + jr*LDSC + cl];
                float gr1 = scr[0*16*LDSC + (jr+1)*LDSC + cl];
                float gz1 = scr[1*16*LDSC + (jr+1)*LDSC + cl];
                float gn1 = scr[2*16*LDSC + (jr+1)*LDSC + cl];

                __nv_bfloat162 hh2 = *(__nv_bfloat162*)(sm + SM_HHI + (size_t)c*LDH*2 + j*2);
                __nv_bfloat162 hl2 = *(__nv_bfloat162*)(sm + SM_HLO + (size_t)c*LDH*2 + j*2);
                float ho0 = __bfloat162float(hh2.x) + __bfloat162float(hl2.x);
                float ho1 = __bfloat162float(hh2.y) + __bfloat162float(hl2.y);

                float r0 = sigf(gr0 + fmaf(xt, cwr0, cbr0));
                float z0 = sigf(gz0 + fmaf(xt, cwz0, cbz0));
                float n0 = tanh_f(fmaf(xt, cwn0, cbi0) + r0 * (gn0 + cbh0));
                float h0 = n0 + z0 * (ho0 - n0);

                float r1 = sigf(gr1 + fmaf(xt, cwr1, cbr1));
                float z1 = sigf(gz1 + fmaf(xt, cwz1, cbz1));
                float n1 = tanh_f(fmaf(xt, cwn1, cbi1) + r1 * (gn1 + cbh1));
                float h1 = n1 + z1 * (ho1 - n1);

                __nv_bfloat16 h0h = __float2bfloat16(h0);
                __nv_bfloat16 h1h = __float2bfloat16(h1);
                __nv_bfloat16 h0l = __float2bfloat16(h0 - __bfloat162float(h0h));
                __nv_bfloat16 h1l = __float2bfloat16(h1 - __bfloat162float(h1h));
                __nv_bfloat162 sh; sh.x = h0h; sh.y = h1h;
                __nv_bfloat162 sl; sl.x = h0l; sl.y = h1l;
                *(__nv_bfloat162*)(sm + SM_HHI + (size_t)c*LDH*2 + j*2) = sh;
                *(__nv_bfloat162*)(sm + SM_HLO + (size_t)c*LDH*2 + j*2) = sl;
            }
            __syncwarp();
        }
        __syncwarp();
    }

    // ---- final projection ----
    {
        const int c = tid;
        const int b = c & 127;
        const int f = f0 + (c >> 7);
        if (f < FF) {
            float hv[GH];
#pragma unroll
            for (int k2 = 0; k2 < 32; k2++) {
                __nv_bfloat162 a  = *(__nv_bfloat162*)(sm + SM_HHI + (size_t)c*LDH*2 + k2*4);
                __nv_bfloat162 bl = *(__nv_bfloat162*)(sm + SM_HLO + (size_t)c*LDH*2 + k2*4);
                hv[2*k2]   = __bfloat162float(a.x) + __bfloat162float(bl.x);
                hv[2*k2+1] = __bfloat162float(a.y) + __bfloat162float(bl.y);
            }
            const size_t ob = ((size_t)b * FF + f) * HID;
#pragma unroll 1
            for (int o = 0; o < HID; o++) {
                float a0 = bslsm[o];
                float a1 = bslsm[HID + o];
#pragma unroll
                for (int k = 0; k < GH; k++) {
                    a0 = fmaf(wslsm[o * GH + k], hv[k], a0);
                    a1 = fmaf(wslsm[(HID + o) * GH + k], hv[k], a1);
                }
                d_As[ob + o] = sigf(a0);
                d_gs[ob + o] = a1;
            }
        }
    }
}

// ---------------- fast branch ----------------
__global__ void __launch_bounds__(256) pass1_kernel(
    const float* __restrict__ x, const float* __restrict__ w_in)
{
    int q = blockIdx.x * blockDim.x + threadIdx.x;
    if (q >= BB * NCH) return;
    int b = q / NCH, ch = q % NCH;
    float win[HID], P[HID], c[HID];
#pragma unroll
    for (int i = 0; i < HID; i++) { win[i] = w_in[i]; P[i] = 1.0f; c[i] = 0.0f; }
    const int t0 = ch * CCH;
    const float* xb = x + (size_t)b * TT;
#pragma unroll 1
    for (int blk = 0; blk < CCH / 16; blk++) {
        int t = t0 + blk * 16;
        int j = (t >> 4) - 1; if (j < 0) j = 0;
        const float4* ap = (const float4*)(d_As + ((size_t)b * FF + j) * HID);
        const float4* gp = (const float4*)(d_gs + ((size_t)b * FF + j) * HID);
        float4 Aa = ap[0], Ab = ap[1], ga = gp[0], gb2 = gp[1];
        float A[HID] = {Aa.x, Aa.y, Aa.z, Aa.w, Ab.x, Ab.y, Ab.z, Ab.w};
        float g[HID] = {ga.x, ga.y, ga.z, ga.w, gb2.x, gb2.y, gb2.z, gb2.w};
        float wg[HID], a16[HID];
#pragma unroll
        for (int i = 0; i < HID; i++) {
            wg[i] = win[i] * g[i];
            float a2 = A[i]*A[i], a4 = a2*a2, a8 = a4*a4;
            a16[i] = a8*a8;
        }
        const float4* xv = (const float4*)(xb + t);
#pragma unroll
        for (int s4 = 0; s4 < 4; s4++) {
            float4 xq = xv[s4];
            float xsv[4] = {xq.x, xq.y, xq.z, xq.w};
#pragma unroll
            for (int s = 0; s < 4; s++)
#pragma unroll
                for (int i = 0; i < HID; i++)
                    c[i] = fmaf(A[i], c[i], xsv[s] * wg[i]);
        }
#pragma unroll
        for (int i = 0; i < HID; i++) P[i] *= a16[i];
    }
    const size_t base = ((size_t)b * NCH + ch) * HID;
#pragma unroll
    for (int i = 0; i < HID; i++) { d_P[base + i] = P[i]; d_c[base + i] = c[i]; }
}

__global__ void __launch_bounds__(256) scan_kernel() {
    int gw   = (blockIdx.x * blockDim.x + threadIdx.x) >> 5;
    int lane = threadIdx.x & 31;
    int b = gw >> 3, i = gw & 7;
    float P[8], c[8];
#pragma unroll
    for (int s = 0; s < 8; s++) {
        size_t idx = ((size_t)b * NCH + (lane * 8 + s)) * HID + i;
        P[s] = d_P[idx]; c[s] = d_c[idx];
    }
    float Pt = 1.0f, ct = 0.0f;
#pragma unroll
    for (int s = 0; s < 8; s++) { ct = fmaf(P[s], ct, c[s]); Pt *= P[s]; }
#pragma unroll
    for (int off = 1; off < 32; off <<= 1) {
        float Pp = __shfl_up_sync(0xffffffffu, Pt, off);
        float cp = __shfl_up_sync(0xffffffffu, ct, off);
        if (lane >= off) { ct = fmaf(Pt, cp, ct); Pt *= Pp; }
    }
    float h = __shfl_up_sync(0xffffffffu, ct, 1);
    if (lane == 0) h = 0.0f;
#pragma unroll
    for (int s = 0; s < 8; s++) {
        size_t idx = ((size_t)b * NCH + (lane * 8 + s)) * HID + i;
        d_H0[idx] = h;
        h = fmaf(P[s], h, c[s]);
    }
}

__global__ void __launch_bounds__(256) pass2_kernel(
    const float* __restrict__ x, const float* __restrict__ w_in,
    const float* __restrict__ w_out, float* __restrict__ y)
{
    int q = blockIdx.x * blockDim.x + threadIdx.x;
    if (q >= BB * NCH) return;
    int b = q / NCH, ch = q % NCH;
    float win[HID], wo[HID], h[HID];
#pragma unroll
    for (int i = 0; i < HID; i++) {
        win[i] = w_in[i]; wo[i] = w_out[i];
        h[i] = d_H0[((size_t)b * NCH + ch) * HID + i];
    }
    const int t0 = ch * CCH;
    const float* xb = x + (size_t)b * TT;
    float* yb = y + (size_t)b * TT;
#pragma unroll 1
    for (int blk = 0; blk < CCH / 16; blk++) {
        int t = t0 + blk * 16;
        int j = (t >> 4) - 1; if (j < 0) j = 0;
        const float4* ap = (const float4*)(d_As + ((size_t)b * FF + j) * HID);
        const float4* gp = (const float4*)(d_gs + ((size_t)b * FF + j) * HID);
        float4 Aa = ap[0], Ab = ap[1], ga = gp[0], gb2 = gp[1];
        float A[HID] = {Aa.x, Aa.y, Aa.z, Aa.w, Ab.x, Ab.y, Ab.z, Ab.w};
        float g[HID] = {ga.x, ga.y, ga.z, ga.w, gb2.x, gb2.y, gb2.z, gb2.w};
        float wg[HID];
#pragma unroll
        for (int i = 0; i < HID; i++) wg[i] = win[i] * g[i];
        const float4* xv = (const float4*)(xb + t);
#pragma unroll
        for (int s4 = 0; s4 < 4; s4++) {
            float4 xq = xv[s4];
            float xsv[4] = {xq.x, xq.y, xq.z, xq.w};
#pragma unroll
            for (int s = 0; s < 4; s++) {
#pragma unroll
                for (int i = 0; i < HID; i++)
                    h[i] = fmaf(A[i], h[i], xsv[s] * wg[i]);
                float yv = 0.0f;
#pragma unroll
                for (int i = 0; i < HID; i++) yv = fmaf(h[i], wo[i], yv);
                yb[t + s4 * 4 + s] = yv;
            }
        }
    }
}

extern "C" void kernel_launch(void* const* d_in, const int* in_sizes, int n_in,
                              void* d_out, int out_size) {
    const float* x    = (const float*)d_in[0];
    const float* w_in = (const float*)d_in[1];
    const float* w_out= (const float*)d_in[2];
    const float* w_ih = (const float*)d_in[3];
    const float* w_hh = (const float*)d_in[4];
    const float* b_ih = (const float*)d_in[5];
    const float* b_hh = (const float*)d_in[6];
    const float* w_sl = (const float*)d_in[7];
    const float* b_sl = (const float*)d_in[8];
    float* y = (float*)d_out;

    static int configured = 0;
    if (!configured) {
        cudaFuncSetAttribute(slow_wmma_kernel,
                             cudaFuncAttributeMaxDynamicSharedMemorySize, SM_BYTES);
        configured = 1;
    }

    init_cpar_kernel<<<1, GH>>>(w_ih, b_ih, b_hh);
    slow_wmma_kernel<<<2048, 256, SM_BYTES>>>(x, w_hh, w_sl, b_sl);
    pass1_kernel<<<(BB * NCH) / 256, 256>>>(x, w_in);
    scan_kernel<<<(BB * HID * 32) / 256, 256>>>();
    pass2_kernel<<<(BB * NCH) / 256, 256>>>(x, w_in, w_out, y);
}

// round 7
// speedup vs baseline: 2.7514x; 1.3520x over previous
#include <cuda_runtime.h>
#include <cuda_fp16.h>
#include <mma.h>
#include <math.h>
#include <stdint.h>

using namespace nvcuda;

#define BB   128
#define TT   65536
#define DELTA 16
#define LS   32
#define HID  8
#define GH   64
#define ODIM 16
#define FF   4095
#define CCH  256
#define NCH  (TT/CCH)

typedef unsigned int u32;

// ---------------- device scratch ----------------
__device__ float d_As[(size_t)BB * FF * HID];
__device__ float d_gs[(size_t)BB * FF * HID];
__device__ float d_P [BB * NCH * HID];
__device__ float d_c [BB * NCH * HID];
__device__ float d_H0[BB * NCH * HID];
__device__ float d_cpar[GH * 8];

__device__ __forceinline__ float sigf(float v) {
    return __fdividef(1.0f, 1.0f + __expf(-v));
}
__device__ __forceinline__ float tanh_f(float v) {
    v = fminf(fmaxf(v, -15.0f), 15.0f);
    float e = __expf(-2.0f * v);
    return __fdividef(1.0f - e, 1.0f + e);
}

__global__ void init_cpar_kernel(const float* __restrict__ w_ih,
                                 const float* __restrict__ b_ih,
                                 const float* __restrict__ b_hh) {
    int j = threadIdx.x;
    if (j < GH) {
        d_cpar[j*8+0] = w_ih[j];
        d_cpar[j*8+1] = w_ih[GH + j];
        d_cpar[j*8+2] = w_ih[2*GH + j];
        d_cpar[j*8+3] = b_ih[j]      + b_hh[j];
        d_cpar[j*8+4] = b_ih[GH + j] + b_hh[GH + j];
        d_cpar[j*8+5] = b_ih[2*GH + j];
        d_cpar[j*8+6] = b_hh[2*GH + j];
        d_cpar[j*8+7] = 0.0f;
    }
}

// ---------------- smem layout (bytes) ----------------
#define LDW   72
#define LDH   72
#define LDS_X 33
#define LDSC  36
#define SM_WHI  0
#define SM_WLO  (SM_WHI + 192*LDW*2)         // 27648
#define SM_H    (SM_WLO + 192*LDW*2)         // 55296
#define SM_XS   (SM_H + 256*LDH*2)           // 92160
#define SM_SCR  (SM_XS + 256*LDS_X*4)        // 125952
#define SCR_WARP (3*16*LDSC)
#define SM_CPAR (SM_SCR + 8*SCR_WARP*4)      // 181248
#define SM_WSL  (SM_CPAR + GH*8*4)           // 183296
#define SM_BSL  (SM_WSL + ODIM*GH*4)         // 187392
#define SM_BYTES (SM_BSL + 64)               // 187456

// grid = 2048 CTAs, 256 threads. CTA covers frames {2c, 2c+1} x 128 batch rows.
// Warp w owns sequence columns [32w, 32w+32) — fully independent GRUs.
__global__ void __launch_bounds__(256, 1) slow_wmma_kernel(
    const float* __restrict__ x,
    const float* __restrict__ w_hh,
    const float* __restrict__ w_sl,
    const float* __restrict__ b_sl)
{
    extern __shared__ char sm[];
    const int tid  = threadIdx.x;
    const int wid  = tid >> 5;
    const int lane = tid & 31;
    const int f0   = blockIdx.x * 2;
    const int cb   = wid * 32;

    __half* WHI = (__half*)(sm + SM_WHI);
    __half* WLO = (__half*)(sm + SM_WLO);
    __half* HS  = (__half*)(sm + SM_H);
    float* xs     = (float*)(sm + SM_XS);
    float* scr    = (float*)(sm + SM_SCR) + wid * SCR_WARP;
    float* cparsm = (float*)(sm + SM_CPAR);
    float* wslsm  = (float*)(sm + SM_WSL);
    float* bslsm  = (float*)(sm + SM_BSL);

    // ---- prologue ----
    for (int i = tid; i < 192 * GH; i += 256) {
        int g = i >> 6, k = i & 63;
        float v = w_hh[i];
        __half hi = __float2half_rn(v);
        __half lo = __float2half_rn(v - __half2float(hi));
        WHI[g * LDW + k] = hi;
        WLO[g * LDW + k] = lo;
    }
    for (int i = tid; i < (256 * LDH * 2) / 4; i += 256)
        ((u32*)(sm + SM_H))[i] = 0u;
    {
        int c = tid;
        int b = c & 127;
        int f = f0 + (c >> 7); if (f > FF - 1) f = FF - 1;
        const float* xp = x + (size_t)b * TT + (size_t)f * DELTA;
#pragma unroll
        for (int t = 0; t < LS; t++) xs[c * LDS_X + t] = xp[t];
    }
    for (int i = tid; i < GH * 8;    i += 256) cparsm[i] = d_cpar[i];
    for (int i = tid; i < ODIM * GH; i += 256) wslsm[i]  = w_sl[i];
    if (tid < ODIM) bslsm[tid] = b_sl[tid];
    __syncthreads();

    const int g8 = lane >> 3;
    const int jr = (lane & 7) * 2;

    // ---- 32 GRU steps ----
#pragma unroll 1
    for (int t = 0; t < LS; t++) {
        // load B fragments (H fp16) for this warp's 32 columns
        wmma::fragment<wmma::matrix_b, 16,16,16, __half, wmma::col_major> bF[4][2];
#pragma unroll
        for (int kt = 0; kt < 4; kt++)
#pragma unroll
            for (int nt = 0; nt < 2; nt++)
                wmma::load_matrix_sync(bF[kt][nt], HS + (size_t)(cb + nt*16) * LDH + kt*16, LDH);

#pragma unroll 1
        for (int mg = 0; mg < 4; mg++) {
            wmma::fragment<wmma::accumulator, 16,16,16, float> acc[3][2];
#pragma unroll
            for (int kind = 0; kind < 3; kind++)
#pragma unroll
                for (int nt = 0; nt < 2; nt++)
                    wmma::fill_fragment(acc[kind][nt], 0.0f);

#pragma unroll
            for (int kind = 0; kind < 3; kind++) {
                const int mi = kind * 4 + mg;
#pragma unroll
                for (int kt = 0; kt < 4; kt++) {
                    wmma::fragment<wmma::matrix_a, 16,16,16, __half, wmma::row_major> aHI, aLO;
                    wmma::load_matrix_sync(aHI, WHI + (size_t)(mi*16) * LDW + kt*16, LDW);
                    wmma::load_matrix_sync(aLO, WLO + (size_t)(mi*16) * LDW + kt*16, LDW);
#pragma unroll
                    for (int nt = 0; nt < 2; nt++) {
                        wmma::mma_sync(acc[kind][nt], aHI, bF[kt][nt], acc[kind][nt]);
                        wmma::mma_sync(acc[kind][nt], aLO, bF[kt][nt], acc[kind][nt]);
                    }
                }
            }
#pragma unroll
            for (int kind = 0; kind < 3; kind++)
#pragma unroll
                for (int nt = 0; nt < 2; nt++)
                    wmma::store_matrix_sync(scr + kind*16*LDSC + nt*16, acc[kind][nt], LDSC, wmma::mem_row_major);
            __syncwarp();

            // nonlinearities: lane handles rows j, j+1 for 8 columns
            const int j = mg * 16 + jr;
            const float* cp0 = cparsm + j * 8;
            const float* cp1 = cparsm + (j + 1) * 8;
            const float cwr0 = cp0[0], cwz0 = cp0[1], cwn0 = cp0[2], cbr0 = cp0[3],
                        cbz0 = cp0[4], cbi0 = cp0[5], cbh0 = cp0[6];
            const float cwr1 = cp1[0], cwz1 = cp1[1], cwn1 = cp1[2], cbr1 = cp1[3],
                        cbz1 = cp1[4], cbi1 = cp1[5], cbh1 = cp1[6];
#pragma unroll
            for (int i = 0; i < 8; i++) {
                const int cl = g8 * 8 + i;
                const int c  = cb + cl;
                const float xt = xs[c * LDS_X + t];
                float gr0 = scr[0*16*LDSC + jr*LDSC + cl];
                float gz0 = scr[1*16*LDSC + jr*LDSC + cl];
                float gn0 = scr[2*16*LDSC + jr*LDSC + cl];
                float gr1 = scr[0*16*LDSC + (jr+1)*LDSC + cl];
                float gz1 = scr[1*16*LDSC + (jr+1)*LDSC + cl];
                float gn1 = scr[2*16*LDSC + (jr+1)*LDSC + cl];

                __half2 hh2 = *(__half2*)(sm + SM_H + (size_t)c*LDH*2 + j*2);
                float ho0 = __half2float(hh2.x);
                float ho1 = __half2float(hh2.y);

                float r0 = sigf(gr0 + fmaf(xt, cwr0, cbr0));
                float z0 = sigf(gz0 + fmaf(xt, cwz0, cbz0));
                float n0 = tanh_f(fmaf(xt, cwn0, cbi0) + r0 * (gn0 + cbh0));
                float h0 = n0 + z0 * (ho0 - n0);

                float r1 = sigf(gr1 + fmaf(xt, cwr1, cbr1));
                float z1 = sigf(gz1 + fmaf(xt, cwz1, cbz1));
                float n1 = tanh_f(fmaf(xt, cwn1, cbi1) + r1 * (gn1 + cbh1));
                float h1 = n1 + z1 * (ho1 - n1);

                __half2 sh;
                sh.x = __float2half_rn(h0);
                sh.y = __float2half_rn(h1);
                *(__half2*)(sm + SM_H + (size_t)c*LDH*2 + j*2) = sh;
            }
            __syncwarp();
        }
        __syncwarp();
    }

    // ---- final projection ----
    {
        const int c = tid;
        const int b = c & 127;
        const int f = f0 + (c >> 7);
        if (f < FF) {
            float hv[GH];
#pragma unroll
            for (int k2 = 0; k2 < 32; k2++) {
                __half2 a = *(__half2*)(sm + SM_H + (size_t)c*LDH*2 + k2*4);
                hv[2*k2]   = __half2float(a.x);
                hv[2*k2+1] = __half2float(a.y);
            }
            const size_t ob = ((size_t)b * FF + f) * HID;
#pragma unroll 1
            for (int o = 0; o < HID; o++) {
                float a0 = bslsm[o];
                float a1 = bslsm[HID + o];
#pragma unroll
                for (int k = 0; k < GH; k++) {
                    a0 = fmaf(wslsm[o * GH + k], hv[k], a0);
                    a1 = fmaf(wslsm[(HID + o) * GH + k], hv[k], a1);
                }
                d_As[ob + o] = sigf(a0);
                d_gs[ob + o] = a1;
            }
        }
    }
}

// ---------------- fast branch ----------------
__global__ void __launch_bounds__(256) pass1_kernel(
    const float* __restrict__ x, const float* __restrict__ w_in)
{
    int q = blockIdx.x * blockDim.x + threadIdx.x;
    if (q >= BB * NCH) return;
    int b = q / NCH, ch = q % NCH;
    float win[HID], P[HID], c[HID];
#pragma unroll
    for (int i = 0; i < HID; i++) { win[i] = w_in[i]; P[i] = 1.0f; c[i] = 0.0f; }
    const int t0 = ch * CCH;
    const float* xb = x + (size_t)b * TT;
#pragma unroll 1
    for (int blk = 0; blk < CCH / 16; blk++) {
        int t = t0 + blk * 16;
        int j = (t >> 4) - 1; if (j < 0) j = 0;
        const float4* ap = (const float4*)(d_As + ((size_t)b * FF + j) * HID);
        const float4* gp = (const float4*)(d_gs + ((size_t)b * FF + j) * HID);
        float4 Aa = ap[0], Ab = ap[1], ga = gp[0], gb2 = gp[1];
        float A[HID] = {Aa.x, Aa.y, Aa.z, Aa.w, Ab.x, Ab.y, Ab.z, Ab.w};
        float g[HID] = {ga.x, ga.y, ga.z, ga.w, gb2.x, gb2.y, gb2.z, gb2.w};
        float wg[HID], a16[HID];
#pragma unroll
        for (int i = 0; i < HID; i++) {
            wg[i] = win[i] * g[i];
            float a2 = A[i]*A[i], a4 = a2*a2, a8 = a4*a4;
            a16[i] = a8*a8;
        }
        const float4* xv = (const float4*)(xb + t);
#pragma unroll
        for (int s4 = 0; s4 < 4; s4++) {
            float4 xq = xv[s4];
            float xsv[4] = {xq.x, xq.y, xq.z, xq.w};
#pragma unroll
            for (int s = 0; s < 4; s++)
#pragma unroll
                for (int i = 0; i < HID; i++)
                    c[i] = fmaf(A[i], c[i], xsv[s] * wg[i]);
        }
#pragma unroll
        for (int i = 0; i < HID; i++) P[i] *= a16[i];
    }
    const size_t base = ((size_t)b * NCH + ch) * HID;
#pragma unroll
    for (int i = 0; i < HID; i++) { d_P[base + i] = P[i]; d_c[base + i] = c[i]; }
}

__global__ void __launch_bounds__(256) scan_kernel() {
    int gw   = (blockIdx.x * blockDim.x + threadIdx.x) >> 5;
    int lane = threadIdx.x & 31;
    int b = gw >> 3, i = gw & 7;
    float P[8], c[8];
#pragma unroll
    for (int s = 0; s < 8; s++) {
        size_t idx = ((size_t)b * NCH + (lane * 8 + s)) * HID + i;
        P[s] = d_P[idx]; c[s] = d_c[idx];
    }
    float Pt = 1.0f, ct = 0.0f;
#pragma unroll
    for (int s = 0; s < 8; s++) { ct = fmaf(P[s], ct, c[s]); Pt *= P[s]; }
#pragma unroll
    for (int off = 1; off < 32; off <<= 1) {
        float Pp = __shfl_up_sync(0xffffffffu, Pt, off);
        float cp = __shfl_up_sync(0xffffffffu, ct, off);
        if (lane >= off) { ct = fmaf(Pt, cp, ct); Pt *= Pp; }
    }
    float h = __shfl_up_sync(0xffffffffu, ct, 1);
    if (lane == 0) h = 0.0f;
#pragma unroll
    for (int s = 0; s < 8; s++) {
        size_t idx = ((size_t)b * NCH + (lane * 8 + s)) * HID + i;
        d_H0[idx] = h;
        h = fmaf(P[s], h, c[s]);
    }
}

__global__ void __launch_bounds__(256) pass2_kernel(
    const float* __restrict__ x, const float* __restrict__ w_in,
    const float* __restrict__ w_out, float* __restrict__ y)
{
    int q = blockIdx.x * blockDim.x + threadIdx.x;
    if (q >= BB * NCH) return;
    int b = q / NCH, ch = q % NCH;
    float win[HID], wo[HID], h[HID];
#pragma unroll
    for (int i = 0; i < HID; i++) {
        win[i] = w_in[i]; wo[i] = w_out[i];
        h[i] = d_H0[((size_t)b * NCH + ch) * HID + i];
    }
    const int t0 = ch * CCH;
    const float* xb = x + (size_t)b * TT;
    float* yb = y + (size_t)b * TT;
#pragma unroll 1
    for (int blk = 0; blk < CCH / 16; blk++) {
        int t = t0 + blk * 16;
        int j = (t >> 4) - 1; if (j < 0) j = 0;
        const float4* ap = (const float4*)(d_As + ((size_t)b * FF + j) * HID);
        const float4* gp = (const float4*)(d_gs + ((size_t)b * FF + j) * HID);
        float4 Aa = ap[0], Ab = ap[1], ga = gp[0], gb2 = gp[1];
        float A[HID] = {Aa.x, Aa.y, Aa.z, Aa.w, Ab.x, Ab.y, Ab.z, Ab.w};
        float g[HID] = {ga.x, ga.y, ga.z, ga.w, gb2.x, gb2.y, gb2.z, gb2.w};
        float wg[HID];
#pragma unroll
        for (int i = 0; i < HID; i++) wg[i] = win[i] * g[i];
        const float4* xv = (const float4*)(xb + t);
#pragma unroll
        for (int s4 = 0; s4 < 4; s4++) {
            float4 xq = xv[s4];
            float xsv[4] = {xq.x, xq.y, xq.z, xq.w};
#pragma unroll
            for (int s = 0; s < 4; s++) {
#pragma unroll
                for (int i = 0; i < HID; i++)
                    h[i] = fmaf(A[i], h[i], xsv[s] * wg[i]);
                float yv = 0.0f;
#pragma unroll
                for (int i = 0; i < HID; i++) yv = fmaf(h[i], wo[i], yv);
                yb[t + s4 * 4 + s] = yv;
            }
        }
    }
}

extern "C" void kernel_launch(void* const* d_in, const int* in_sizes, int n_in,
                              void* d_out, int out_size) {
    const float* x    = (const float*)d_in[0];
    const float* w_in = (const float*)d_in[1];
    const float* w_out= (const float*)d_in[2];
    const float* w_ih = (const float*)d_in[3];
    const float* w_hh = (const float*)d_in[4];
    const float* b_ih = (const float*)d_in[5];
    const float* b_hh = (const float*)d_in[6];
    const float* w_sl = (const float*)d_in[7];
    const float* b_sl = (const float*)d_in[8];
    float* y = (float*)d_out;

    static int configured = 0;
    if (!configured) {
        cudaFuncSetAttribute(slow_wmma_kernel,
                             cudaFuncAttributeMaxDynamicSharedMemorySize, SM_BYTES);
        configured = 1;
    }

    init_cpar_kernel<<<1, GH>>>(w_ih, b_ih, b_hh);
    slow_wmma_kernel<<<2048, 256, SM_BYTES>>>(x, w_hh, w_sl, b_sl);
    pass1_kernel<<<(BB * NCH) / 256, 256>>>(x, w_in);
    scan_kernel<<<(BB * HID * 32) / 256, 256>>>();
    pass2_kernel<<<(BB * NCH) / 256, 256>>>(x, w_in, w_out, y);
}

// round 9
// speedup vs baseline: 2.7536x; 1.0008x over previous
#include <cuda_runtime.h>
#include <cuda_fp16.h>
#include <mma.h>
#include <math.h>
#include <stdint.h>

using namespace nvcuda;

#define BB   128
#define TT   65536
#define DELTA 16
#define LS   32
#define HID  8
#define GH   64
#define ODIM 16
#define FF   4095
#define CCH  256
#define NCH  (TT/CCH)

typedef unsigned int u32;

// ---------------- device scratch ----------------
__device__ float d_As[(size_t)BB * FF * HID];
__device__ float d_gs[(size_t)BB * FF * HID];
__device__ float d_P [BB * NCH * HID];
__device__ float d_c [BB * NCH * HID];
__device__ float d_H0[BB * NCH * HID];
__device__ float d_cpar[GH * 8];

__device__ __forceinline__ float sigf(float v) {
    return __fdividef(1.0f, 1.0f + __expf(-v));
}
__device__ __forceinline__ float tanh_f(float v) {
    v = fminf(fmaxf(v, -15.0f), 15.0f);
    float e = __expf(-2.0f * v);
    return __fdividef(1.0f - e, 1.0f + e);
}

__global__ void init_cpar_kernel(const float* __restrict__ w_ih,
                                 const float* __restrict__ b_ih,
                                 const float* __restrict__ b_hh) {
    int j = threadIdx.x;
    if (j < GH) {
        d_cpar[j*8+0] = w_ih[j];
        d_cpar[j*8+1] = w_ih[GH + j];
        d_cpar[j*8+2] = w_ih[2*GH + j];
        d_cpar[j*8+3] = b_ih[j]      + b_hh[j];
        d_cpar[j*8+4] = b_ih[GH + j] + b_hh[GH + j];
        d_cpar[j*8+5] = b_ih[2*GH + j];
        d_cpar[j*8+6] = b_hh[2*GH + j];
        d_cpar[j*8+7] = 0.0f;
    }
}

// ---------------- smem layout (bytes) ----------------
#define LDW   72
#define LDH   72
#define LDS_X 33
#define LDSC  36
#define SM_WHI  0
#define SM_WLO  (SM_WHI + 192*LDW*2)         // 27648
#define SM_H    (SM_WLO + 192*LDW*2)         // 55296
#define SM_XS   (SM_H + 256*LDH*2)           // 92160
#define SM_SCR  (SM_XS + 256*LDS_X*4)        // 125952
#define SCR_WARP (3*16*LDSC)
#define SM_CPAR (SM_SCR + 8*SCR_WARP*4)      // 181248
#define SM_WSL  (SM_CPAR + GH*8*4)           // 183296
#define SM_BSL  (SM_WSL + ODIM*GH*4)         // 187392
#define SM_BYTES (SM_BSL + 64)               // 187456

// grid = 2048 CTAs, 256 threads. CTA covers frames {2c, 2c+1} x 128 batch rows.
// Warp w owns sequence columns [32w, 32w+32) — fully independent GRUs.
__global__ void __launch_bounds__(256, 1) slow_wmma_kernel(
    const float* __restrict__ x,
    const float* __restrict__ w_hh,
    const float* __restrict__ w_sl,
    const float* __restrict__ b_sl)
{
    extern __shared__ char sm[];
    const int tid  = threadIdx.x;
    const int wid  = tid >> 5;
    const int lane = tid & 31;
    const int f0   = blockIdx.x * 2;
    const int cb   = wid * 32;

    __half* WHI = (__half*)(sm + SM_WHI);
    __half* WLO = (__half*)(sm + SM_WLO);
    __half* HS  = (__half*)(sm + SM_H);
    float* xs     = (float*)(sm + SM_XS);
    float* scr    = (float*)(sm + SM_SCR) + wid * SCR_WARP;
    float* cparsm = (float*)(sm + SM_CPAR);
    float* wslsm  = (float*)(sm + SM_WSL);
    float* bslsm  = (float*)(sm + SM_BSL);

    // ---- prologue ----
    for (int i = tid; i < 192 * GH; i += 256) {
        int g = i >> 6, k = i & 63;
        float v = w_hh[i];
        __half hi = __float2half_rn(v);
        __half lo = __float2half_rn(v - __half2float(hi));
        WHI[g * LDW + k] = hi;
        WLO[g * LDW + k] = lo;
    }
    for (int i = tid; i < (256 * LDH * 2) / 4; i += 256)
        ((u32*)(sm + SM_H))[i] = 0u;
    {
        int c = tid;
        int b = c & 127;
        int f = f0 + (c >> 7); if (f > FF - 1) f = FF - 1;
        const float* xp = x + (size_t)b * TT + (size_t)f * DELTA;
#pragma unroll
        for (int t = 0; t < LS; t++) xs[c * LDS_X + t] = xp[t];
    }
    for (int i = tid; i < GH * 8;    i += 256) cparsm[i] = d_cpar[i];
    for (int i = tid; i < ODIM * GH; i += 256) wslsm[i]  = w_sl[i];
    if (tid < ODIM) bslsm[tid] = b_sl[tid];
    __syncthreads();

    const int g8 = lane >> 3;
    const int jr = (lane & 7) * 2;

    // ---- 32 GRU steps ----
#pragma unroll 1
    for (int t = 0; t < LS; t++) {
        // load B fragments (H fp16) for this warp's 32 columns
        wmma::fragment<wmma::matrix_b, 16,16,16, __half, wmma::col_major> bF[4][2];
#pragma unroll
        for (int kt = 0; kt < 4; kt++)
#pragma unroll
            for (int nt = 0; nt < 2; nt++)
                wmma::load_matrix_sync(bF[kt][nt], HS + (size_t)(cb + nt*16) * LDH + kt*16, LDH);

#pragma unroll 1
        for (int mg = 0; mg < 4; mg++) {
            // split accumulators: hi-product and lo-product kept separate
            // => 12 independent HMMA dependency chains of depth 4 (was 6 x depth 8)
            wmma::fragment<wmma::accumulator, 16,16,16, float> accH[3][2], accL[3][2];
#pragma unroll
            for (int kind = 0; kind < 3; kind++)
#pragma unroll
                for (int nt = 0; nt < 2; nt++) {
                    wmma::fill_fragment(accH[kind][nt], 0.0f);
                    wmma::fill_fragment(accL[kind][nt], 0.0f);
                }

            // kt-outer / kind-inner: consecutive MMAs on the same chain are
            // ~12 wmma apart -> accumulator RAW latency fully covered
#pragma unroll
            for (int kt = 0; kt < 4; kt++) {
#pragma unroll
                for (int kind = 0; kind < 3; kind++) {
                    const int mi = kind * 4 + mg;
                    wmma::fragment<wmma::matrix_a, 16,16,16, __half, wmma::row_major> aHI, aLO;
                    wmma::load_matrix_sync(aHI, WHI + (size_t)(mi*16) * LDW + kt*16, LDW);
                    wmma::load_matrix_sync(aLO, WLO + (size_t)(mi*16) * LDW + kt*16, LDW);
                    wmma::mma_sync(accH[kind][0], aHI, bF[kt][0], accH[kind][0]);
                    wmma::mma_sync(accH[kind][1], aHI, bF[kt][1], accH[kind][1]);
                    wmma::mma_sync(accL[kind][0], aLO, bF[kt][0], accL[kind][0]);
                    wmma::mma_sync(accL[kind][1], aLO, bF[kt][1], accL[kind][1]);
                }
            }

            // merge lo into hi, then store
#pragma unroll
            for (int kind = 0; kind < 3; kind++)
#pragma unroll
                for (int nt = 0; nt < 2; nt++) {
#pragma unroll
                    for (int e = 0; e < accH[kind][nt].num_elements; e++)
                        accH[kind][nt].x[e] += accL[kind][nt].x[e];
                    wmma::store_matrix_sync(scr + kind*16*LDSC + nt*16, accH[kind][nt], LDSC, wmma::mem_row_major);
                }
            __syncwarp();

            // nonlinearities: lane handles rows j, j+1 for 8 columns
            const int j = mg * 16 + jr;
            const float* cp0 = cparsm + j * 8;
            const float* cp1 = cparsm + (j + 1) * 8;
            const float cwr0 = cp0[0], cwz0 = cp0[1], cwn0 = cp0[2], cbr0 = cp0[3],
                        cbz0 = cp0[4], cbi0 = cp0[5], cbh0 = cp0[6];
            const float cwr1 = cp1[0], cwz1 = cp1[1], cwn1 = cp1[2], cbr1 = cp1[3],
                        cbz1 = cp1[4], cbi1 = cp1[5], cbh1 = cp1[6];
#pragma unroll
            for (int i = 0; i < 8; i++) {
                const int cl = g8 * 8 + i;
                const int c  = cb + cl;
                const float xt = xs[c * LDS_X + t];
                float gr0 = scr[0*16*LDSC + jr*LDSC + cl];
                float gz0 = scr[1*16*LDSC + jr*LDSC + cl];
                float gn0 = scr[2*16*LDSC + jr*LDSC + cl];
                float gr1 = scr[0*16*LDSC + (jr+1)*LDSC + cl];
                float gz1 = scr[1*16*LDSC + (jr+1)*LDSC + cl];
                float gn1 = scr[2*16*LDSC + (jr+1)*LDSC + cl];

                __half2 hh2 = *(__half2*)(sm + SM_H + (size_t)c*LDH*2 + j*2);
                float ho0 = __half2float(hh2.x);
                float ho1 = __half2float(hh2.y);

                float r0 = sigf(gr0 + fmaf(xt, cwr0, cbr0));
                float z0 = sigf(gz0 + fmaf(xt, cwz0, cbz0));
                float n0 = tanh_f(fmaf(xt, cwn0, cbi0) + r0 * (gn0 + cbh0));
                float h0 = n0 + z0 * (ho0 - n0);

                float r1 = sigf(gr1 + fmaf(xt, cwr1, cbr1));
                float z1 = sigf(gz1 + fmaf(xt, cwz1, cbz1));
                float n1 = tanh_f(fmaf(xt, cwn1, cbi1) + r1 * (gn1 + cbh1));
                float h1 = n1 + z1 * (ho1 - n1);

                __half2 sh;
                sh.x = __float2half_rn(h0);
                sh.y = __float2half_rn(h1);
                *(__half2*)(sm + SM_H + (size_t)c*LDH*2 + j*2) = sh;
            }
            __syncwarp();
        }
        __syncwarp();
    }

    // ---- final projection ----
    {
        const int c = tid;
        const int b = c & 127;
        const int f = f0 + (c >> 7);
        if (f < FF) {
            float hv[GH];
#pragma unroll
            for (int k2 = 0; k2 < 32; k2++) {
                __half2 a = *(__half2*)(sm + SM_H + (size_t)c*LDH*2 + k2*4);
                hv[2*k2]   = __half2float(a.x);
                hv[2*k2+1] = __half2float(a.y);
            }
            const size_t ob = ((size_t)b * FF + f) * HID;
#pragma unroll 1
            for (int o = 0; o < HID; o++) {
                float a0 = bslsm[o];
                float a1 = bslsm[HID + o];
#pragma unroll
                for (int k = 0; k < GH; k++) {
                    a0 = fmaf(wslsm[o * GH + k], hv[k], a0);
                    a1 = fmaf(wslsm[(HID + o) * GH + k], hv[k], a1);
                }
                d_As[ob + o] = sigf(a0);
                d_gs[ob + o] = a1;
            }
        }
    }
}

// ---------------- fast branch ----------------
__global__ void __launch_bounds__(256) pass1_kernel(
    const float* __restrict__ x, const float* __restrict__ w_in)
{
    int q = blockIdx.x * blockDim.x + threadIdx.x;
    if (q >= BB * NCH) return;
    int b = q / NCH, ch = q % NCH;
    float win[HID], P[HID], c[HID];
#pragma unroll
    for (int i = 0; i < HID; i++) { win[i] = w_in[i]; P[i] = 1.0f; c[i] = 0.0f; }
    const int t0 = ch * CCH;
    const float* xb = x + (size_t)b * TT;
#pragma unroll 1
    for (int blk = 0; blk < CCH / 16; blk++) {
        int t = t0 + blk * 16;
        int j = (t >> 4) - 1; if (j < 0) j = 0;
        const float4* ap = (const float4*)(d_As + ((size_t)b * FF + j) * HID);
        const float4* gp = (const float4*)(d_gs + ((size_t)b * FF + j) * HID);
        float4 Aa = ap[0], Ab = ap[1], ga = gp[0], gb2 = gp[1];
        float A[HID] = {Aa.x, Aa.y, Aa.z, Aa.w, Ab.x, Ab.y, Ab.z, Ab.w};
        float g[HID] = {ga.x, ga.y, ga.z, ga.w, gb2.x, gb2.y, gb2.z, gb2.w};
        float wg[HID], a16[HID];
#pragma unroll
        for (int i = 0; i < HID; i++) {
            wg[i] = win[i] * g[i];
            float a2 = A[i]*A[i], a4 = a2*a2, a8 = a4*a4;
            a16[i] = a8*a8;
        }
        const float4* xv = (const float4*)(xb + t);
#pragma unroll
        for (int s4 = 0; s4 < 4; s4++) {
            float4 xq = xv[s4];
            float xsv[4] = {xq.x, xq.y, xq.z, xq.w};
#pragma unroll
            for (int s = 0; s < 4; s++)
#pragma unroll
                for (int i = 0; i < HID; i++)
                    c[i] = fmaf(A[i], c[i], xsv[s] * wg[i]);
        }
#pragma unroll
        for (int i = 0; i < HID; i++) P[i] *= a16[i];
    }
    const size_t base = ((size_t)b * NCH + ch) * HID;
#pragma unroll
    for (int i = 0; i < HID; i++) { d_P[base + i] = P[i]; d_c[base + i] = c[i]; }
}

__global__ void __launch_bounds__(256) scan_kernel() {
    int gw   = (blockIdx.x * blockDim.x + threadIdx.x) >> 5;
    int lane = threadIdx.x & 31;
    int b = gw >> 3, i = gw & 7;
    float P[8], c[8];
#pragma unroll
    for (int s = 0; s < 8; s++) {
        size_t idx = ((size_t)b * NCH + (lane * 8 + s)) * HID + i;
        P[s] = d_P[idx]; c[s] = d_c[idx];
    }
    float Pt = 1.0f, ct = 0.0f;
#pragma unroll
    for (int s = 0; s < 8; s++) { ct = fmaf(P[s], ct, c[s]); Pt *= P[s]; }
#pragma unroll
    for (int off = 1; off < 32; off <<= 1) {
        float Pp = __shfl_up_sync(0xffffffffu, Pt, off);
        float cp = __shfl_up_sync(0xffffffffu, ct, off);
        if (lane >= off) { ct = fmaf(Pt, cp, ct); Pt *= Pp; }
    }
    float h = __shfl_up_sync(0xffffffffu, ct, 1);
    if (lane == 0) h = 0.0f;
#pragma unroll
    for (int s = 0; s < 8; s++) {
        size_t idx = ((size_t)b * NCH + (lane * 8 + s)) * HID + i;
        d_H0[idx] = h;
        h = fmaf(P[s], h, c[s]);
    }
}

__global__ void __launch_bounds__(256) pass2_kernel(
    const float* __restrict__ x, const float* __restrict__ w_in,
    const float* __restrict__ w_out, float* __restrict__ y)
{
    int q = blockIdx.x * blockDim.x + threadIdx.x;
    if (q >= BB * NCH) return;
    int b = q / NCH, ch = q % NCH;
    float win[HID], wo[HID], h[HID];
#pragma unroll
    for (int i = 0; i < HID; i++) {
        win[i] = w_in[i]; wo[i] = w_out[i];
        h[i] = d_H0[((size_t)b * NCH + ch) * HID + i];
    }
    const int t0 = ch * CCH;
    const float* xb = x + (size_t)b * TT;
    float* yb = y + (size_t)b * TT;
#pragma unroll 1
    for (int blk = 0; blk < CCH / 16; blk++) {
        int t = t0 + blk * 16;
        int j = (t >> 4) - 1; if (j < 0) j = 0;
        const float4* ap = (const float4*)(d_As + ((size_t)b * FF + j) * HID);
        const float4* gp = (const float4*)(d_gs + ((size_t)b * FF + j) * HID);
        float4 Aa = ap[0], Ab = ap[1], ga = gp[0], gb2 = gp[1];
        float A[HID] = {Aa.x, Aa.y, Aa.z, Aa.w, Ab.x, Ab.y, Ab.z, Ab.w};
        float g[HID] = {ga.x, ga.y, ga.z, ga.w, gb2.x, gb2.y, gb2.z, gb2.w};
        float wg[HID];
#pragma unroll
        for (int i = 0; i < HID; i++) wg[i] = win[i] * g[i];
        const float4* xv = (const float4*)(xb + t);
#pragma unroll
        for (int s4 = 0; s4 < 4; s4++) {
            float4 xq = xv[s4];
            float xsv[4] = {xq.x, xq.y, xq.z, xq.w};
#pragma unroll
            for (int s = 0; s < 4; s++) {
#pragma unroll
                for (int i = 0; i < HID; i++)
                    h[i] = fmaf(A[i], h[i], xsv[s] * wg[i]);
                float yv = 0.0f;
#pragma unroll
                for (int i = 0; i < HID; i++) yv = fmaf(h[i], wo[i], yv);
                yb[t + s4 * 4 + s] = yv;
            }
        }
    }
}

extern "C" void kernel_launch(void* const* d_in, const int* in_sizes, int n_in,
                              void* d_out, int out_size) {
    const float* x    = (const float*)d_in[0];
    const float* w_in = (const float*)d_in[1];
    const float* w_out= (const float*)d_in[2];
    const float* w_ih = (const float*)d_in[3];
    const float* w_hh = (const float*)d_in[4];
    const float* b_ih = (const float*)d_in[5];
    const float* b_hh = (const float*)d_in[6];
    const float* w_sl = (const float*)d_in[7];
    const float* b_sl = (const float*)d_in[8];
    float* y = (float*)d_out;

    static int configured = 0;
    if (!configured) {
        cudaFuncSetAttribute(slow_wmma_kernel,
                             cudaFuncAttributeMaxDynamicSharedMemorySize, SM_BYTES);
        configured = 1;
    }

    init_cpar_kernel<<<1, GH>>>(w_ih, b_ih, b_hh);
    slow_wmma_kernel<<<2048, 256, SM_BYTES>>>(x, w_hh, w_sl, b_sl);
    pass1_kernel<<<(BB * NCH) / 256, 256>>>(x, w_in);
    scan_kernel<<<(BB * HID * 32) / 256, 256>>>();
    pass2_kernel<<<(BB * NCH) / 256, 256>>>(x, w_in, w_out, y);
}

// round 10
// speedup vs baseline: 4.8861x; 1.7744x over previous
#include <cuda_runtime.h>
#include <cuda_fp16.h>
#include <mma.h>
#include <math.h>
#include <stdint.h>

using namespace nvcuda;

#define BB   128
#define TT   65536
#define DELTA 16
#define LS   32
#define HID  8
#define GH   64
#define ODIM 16
#define FF   4095
#define CCH  256
#define NCH  (TT/CCH)

typedef unsigned int u32;

// ---------------- device scratch ----------------
__device__ float d_As[(size_t)BB * FF * HID];
__device__ float d_gs[(size_t)BB * FF * HID];
__device__ float d_P [BB * NCH * HID];
__device__ float d_c [BB * NCH * HID];
__device__ float d_H0[BB * NCH * HID];
__device__ float d_cpar[GH * 8];

__device__ __forceinline__ float sigf(float v) {
    return __fdividef(1.0f, 1.0f + __expf(-v));
}
__device__ __forceinline__ float tanh_f(float v) {
    v = fminf(fmaxf(v, -15.0f), 15.0f);
    float e = __expf(-2.0f * v);
    return __fdividef(1.0f - e, 1.0f + e);
}

__global__ void init_cpar_kernel(const float* __restrict__ w_ih,
                                 const float* __restrict__ b_ih,
                                 const float* __restrict__ b_hh) {
    int j = threadIdx.x;
    if (j < GH) {
        d_cpar[j*8+0] = w_ih[j];
        d_cpar[j*8+1] = w_ih[GH + j];
        d_cpar[j*8+2] = w_ih[2*GH + j];
        d_cpar[j*8+3] = b_ih[j]      + b_hh[j];
        d_cpar[j*8+4] = b_ih[GH + j] + b_hh[GH + j];
        d_cpar[j*8+5] = b_ih[2*GH + j];
        d_cpar[j*8+6] = b_hh[2*GH + j];
        d_cpar[j*8+7] = 0.0f;
    }
}

// ---------------- smem layout (bytes) ----------------
#define LDW   72
#define LDHH  264            // H row stride in halfs (row-major [k][col]), mult of 8
#define LDS_X 33
#define SM_WHI  0
#define SM_WLO  (SM_WHI + 192*LDW*2)         // 27648
#define SM_H    (SM_WLO + 192*LDW*2)         // 55296
#define SM_XS   (SM_H + 64*LDHH*2)           // 89088  (also probe scratch)
#define SM_CPAR (SM_XS + 256*LDS_X*4)        // 122880
#define SM_WSL  (SM_CPAR + GH*8*4)           // 124928
#define SM_BSL  (SM_WSL + ODIM*GH*4)         // 129024
#define SM_BYTES (SM_BSL + 64)               // 129088

// grid = 2048 CTAs, 256 threads. CTA covers frames {2c, 2c+1} x 128 batch rows.
// Warp w owns sequence columns [32w, 32w+32).
__global__ void __launch_bounds__(256, 1) slow_wmma_kernel(
    const float* __restrict__ x,
    const float* __restrict__ w_hh,
    const float* __restrict__ w_sl,
    const float* __restrict__ b_sl)
{
    extern __shared__ char sm[];
    const int tid  = threadIdx.x;
    const int wid  = tid >> 5;
    const int f0   = blockIdx.x * 2;
    const int cb   = wid * 32;

    __half* WHI = (__half*)(sm + SM_WHI);
    __half* WLO = (__half*)(sm + SM_WLO);
    __half* HS  = (__half*)(sm + SM_H);
    float* xs     = (float*)(sm + SM_XS);
    float* cparsm = (float*)(sm + SM_CPAR);
    float* wslsm  = (float*)(sm + SM_WSL);
    float* bslsm  = (float*)(sm + SM_BSL);

    // ---- probe the wmma accumulator element->(row,col) mapping ----
    // A = I16, B[k][n] = k*16+n  =>  acc(r,c) = 16r + c
    int jm[8], cm[8];
    {
        __half* pA = (__half*)(sm + SM_XS);          // 256 halfs
        __half* pB = pA + 256;                       // 256 halfs
        if (tid < 256) {
            int r = tid >> 4, k = tid & 15;
            pA[tid] = __float2half_rn(r == k ? 1.0f : 0.0f);
            pB[tid] = __float2half_rn((float)tid);   // B[k][n] row-major
        }
        __syncthreads();
        wmma::fragment<wmma::matrix_a, 16,16,16, __half, wmma::row_major> pa;
        wmma::fragment<wmma::matrix_b, 16,16,16, __half, wmma::row_major> pb;
        wmma::fragment<wmma::accumulator, 16,16,16, float> pc;
        wmma::load_matrix_sync(pa, pA, 16);
        wmma::load_matrix_sync(pb, pB, 16);
        wmma::fill_fragment(pc, 0.0f);
        wmma::mma_sync(pc, pa, pb, pc);
#pragma unroll
        for (int e = 0; e < 8; e++) {
            int v = (int)(pc.x[e] + 0.5f);
            jm[e] = v >> 4;
            cm[e] = v & 15;
        }
        __syncthreads();   // done reading probe area before xs overwrites it
    }

    // ---- prologue ----
    for (int i = tid; i < 192 * GH; i += 256) {
        int g = i >> 6, k = i & 63;
        float v = w_hh[i];
        __half hi = __float2half_rn(v);
        __half lo = __float2half_rn(v - __half2float(hi));
        WHI[g * LDW + k] = hi;
        WLO[g * LDW + k] = lo;
    }
    for (int i = tid; i < (64 * LDHH * 2) / 4; i += 256)
        ((u32*)(sm + SM_H))[i] = 0u;
    {
        int c = tid;
        int b = c & 127;
        int f = f0 + (c >> 7); if (f > FF - 1) f = FF - 1;
        const float* xp = x + (size_t)b * TT + (size_t)f * DELTA;
#pragma unroll
        for (int t = 0; t < LS; t++) xs[c * LDS_X + t] = xp[t];
    }
    for (int i = tid; i < GH * 8;    i += 256) cparsm[i] = d_cpar[i];
    for (int i = tid; i < ODIM * GH; i += 256) wslsm[i]  = w_sl[i];
    if (tid < ODIM) bslsm[tid] = b_sl[tid];
    __syncthreads();

    // ---- 32 GRU steps ----
#pragma unroll 1
    for (int t = 0; t < LS; t++) {
        // hoist x_t for this lane's 16 (nt,e) columns
        float xts[16];
#pragma unroll
        for (int e = 0; e < 8; e++) {
            xts[e]     = xs[(cb + cm[e]) * LDS_X + t];
            xts[8 + e] = xs[(cb + 16 + cm[e]) * LDS_X + t];
        }

        // load B fragments (H fp16, row-major [k][col])
        wmma::fragment<wmma::matrix_b, 16,16,16, __half, wmma::row_major> bF[4][2];
#pragma unroll
        for (int kt = 0; kt < 4; kt++)
#pragma unroll
            for (int nt = 0; nt < 2; nt++)
                wmma::load_matrix_sync(bF[kt][nt], HS + (size_t)(kt*16) * LDHH + cb + nt*16, LDHH);

#pragma unroll 1
        for (int mg = 0; mg < 4; mg++) {
            wmma::fragment<wmma::accumulator, 16,16,16, float> acc[3][2];
#pragma unroll
            for (int kind = 0; kind < 3; kind++)
#pragma unroll
                for (int nt = 0; nt < 2; nt++)
                    wmma::fill_fragment(acc[kind][nt], 0.0f);

#pragma unroll
            for (int kind = 0; kind < 3; kind++) {
                const int mi = kind * 4 + mg;
#pragma unroll
                for (int kt = 0; kt < 4; kt++) {
                    wmma::fragment<wmma::matrix_a, 16,16,16, __half, wmma::row_major> aHI, aLO;
                    wmma::load_matrix_sync(aHI, WHI + (size_t)(mi*16) * LDW + kt*16, LDW);
                    wmma::load_matrix_sync(aLO, WLO + (size_t)(mi*16) * LDW + kt*16, LDW);
                    wmma::mma_sync(acc[kind][0], aHI, bF[kt][0], acc[kind][0]);
                    wmma::mma_sync(acc[kind][1], aHI, bF[kt][1], acc[kind][1]);
                    wmma::mma_sync(acc[kind][0], aLO, bF[kt][0], acc[kind][0]);
                    wmma::mma_sync(acc[kind][1], aLO, bF[kt][1], acc[kind][1]);
                }
            }

            // fragment-direct epilogue: no scr, no store_matrix, no syncwarp
#pragma unroll
            for (int e = 0; e < 8; e++) {
                const int j = mg * 16 + jm[e];
                const float4 c0 = ((const float4*)(cparsm + j * 8))[0];
                const float4 c1 = ((const float4*)(cparsm + j * 8))[1];
#pragma unroll
                for (int nt = 0; nt < 2; nt++) {
                    const int c = cb + nt * 16 + cm[e];
                    const float xt = xts[nt * 8 + e];
                    float gr = acc[0][nt].x[e];
                    float gz = acc[1][nt].x[e];
                    float gn = acc[2][nt].x[e];

                    float ho = __half2float(HS[(size_t)j * LDHH + c]);

                    float r = sigf(gr + fmaf(xt, c0.x, c0.w));
                    float z = sigf(gz + fmaf(xt, c0.y, c1.x));
                    float n = tanh_f(fmaf(xt, c0.z, c1.y) + r * (gn + c1.z));
                    float h = n + z * (ho - n);

                    HS[(size_t)j * LDHH + c] = __float2half_rn(h);
                }
            }
        }
        __syncwarp();   // this warp's H writes visible to next step's bF loads
    }

    // ---- final projection ----
    {
        const int c = tid;
        const int b = c & 127;
        const int f = f0 + (c >> 7);
        if (f < FF) {
            float hv[GH];
#pragma unroll
            for (int k = 0; k < GH; k++)
                hv[k] = __half2float(HS[(size_t)k * LDHH + c]);
            const size_t ob = ((size_t)b * FF + f) * HID;
#pragma unroll 1
            for (int o = 0; o < HID; o++) {
                float a0 = bslsm[o];
                float a1 = bslsm[HID + o];
#pragma unroll
                for (int k = 0; k < GH; k++) {
                    a0 = fmaf(wslsm[o * GH + k], hv[k], a0);
                    a1 = fmaf(wslsm[(HID + o) * GH + k], hv[k], a1);
                }
                d_As[ob + o] = sigf(a0);
                d_gs[ob + o] = a1;
            }
        }
    }
}

// ---------------- fast branch ----------------
__global__ void __launch_bounds__(256) pass1_kernel(
    const float* __restrict__ x, const float* __restrict__ w_in)
{
    int q = blockIdx.x * blockDim.x + threadIdx.x;
    if (q >= BB * NCH) return;
    int b = q / NCH, ch = q % NCH;
    float win[HID], P[HID], c[HID];
#pragma unroll
    for (int i = 0; i < HID; i++) { win[i] = w_in[i]; P[i] = 1.0f; c[i] = 0.0f; }
    const int t0 = ch * CCH;
    const float* xb = x + (size_t)b * TT;
#pragma unroll 1
    for (int blk = 0; blk < CCH / 16; blk++) {
        int t = t0 + blk * 16;
        int j = (t >> 4) - 1; if (j < 0) j = 0;
        const float4* ap = (const float4*)(d_As + ((size_t)b * FF + j) * HID);
        const float4* gp = (const float4*)(d_gs + ((size_t)b * FF + j) * HID);
        float4 Aa = ap[0], Ab = ap[1], ga = gp[0], gb2 = gp[1];
        float A[HID] = {Aa.x, Aa.y, Aa.z, Aa.w, Ab.x, Ab.y, Ab.z, Ab.w};
        float g[HID] = {ga.x, ga.y, ga.z, ga.w, gb2.x, gb2.y, gb2.z, gb2.w};
        float wg[HID], a16[HID];
#pragma unroll
        for (int i = 0; i < HID; i++) {
            wg[i] = win[i] * g[i];
            float a2 = A[i]*A[i], a4 = a2*a2, a8 = a4*a4;
            a16[i] = a8*a8;
        }
        const float4* xv = (const float4*)(xb + t);
#pragma unroll
        for (int s4 = 0; s4 < 4; s4++) {
            float4 xq = xv[s4];
            float xsv[4] = {xq.x, xq.y, xq.z, xq.w};
#pragma unroll
            for (int s = 0; s < 4; s++)
#pragma unroll
                for (int i = 0; i < HID; i++)
                    c[i] = fmaf(A[i], c[i], xsv[s] * wg[i]);
        }
#pragma unroll
        for (int i = 0; i < HID; i++) P[i] *= a16[i];
    }
    const size_t base = ((size_t)b * NCH + ch) * HID;
#pragma unroll
    for (int i = 0; i < HID; i++) { d_P[base + i] = P[i]; d_c[base + i] = c[i]; }
}

__global__ void __launch_bounds__(256) scan_kernel() {
    int gw   = (blockIdx.x * blockDim.x + threadIdx.x) >> 5;
    int lane = threadIdx.x & 31;
    int b = gw >> 3, i = gw & 7;
    float P[8], c[8];
#pragma unroll
    for (int s = 0; s < 8; s++) {
        size_t idx = ((size_t)b * NCH + (lane * 8 + s)) * HID + i;
        P[s] = d_P[idx]; c[s] = d_c[idx];
    }
    float Pt = 1.0f, ct = 0.0f;
#pragma unroll
    for (int s = 0; s < 8; s++) { ct = fmaf(P[s], ct, c[s]); Pt *= P[s]; }
#pragma unroll
    for (int off = 1; off < 32; off <<= 1) {
        float Pp = __shfl_up_sync(0xffffffffu, Pt, off);
        float cp = __shfl_up_sync(0xffffffffu, ct, off);
        if (lane >= off) { ct = fmaf(Pt, cp, ct); Pt *= Pp; }
    }
    float h = __shfl_up_sync(0xffffffffu, ct, 1);
    if (lane == 0) h = 0.0f;
#pragma unroll
    for (int s = 0; s < 8; s++) {
        size_t idx = ((size_t)b * NCH + (lane * 8 + s)) * HID + i;
        d_H0[idx] = h;
        h = fmaf(P[s], h, c[s]);
    }
}

__global__ void __launch_bounds__(256) pass2_kernel(
    const float* __restrict__ x, const float* __restrict__ w_in,
    const float* __restrict__ w_out, float* __restrict__ y)
{
    int q = blockIdx.x * blockDim.x + threadIdx.x;
    if (q >= BB * NCH) return;
    int b = q / NCH, ch = q % NCH;
    float win[HID], wo[HID], h[HID];
#pragma unroll
    for (int i = 0; i < HID; i++) {
        win[i] = w_in[i]; wo[i] = w_out[i];
        h[i] = d_H0[((size_t)b * NCH + ch) * HID + i];
    }
    const int t0 = ch * CCH;
    const float* xb = x + (size_t)b * TT;
    float* yb = y + (size_t)b * TT;
#pragma unroll 1
    for (int blk = 0; blk < CCH / 16; blk++) {
        int t = t0 + blk * 16;
        int j = (t >> 4) - 1; if (j < 0) j = 0;
        const float4* ap = (const float4*)(d_As + ((size_t)b * FF + j) * HID);
        const float4* gp = (const float4*)(d_gs + ((size_t)b * FF + j) * HID);
        float4 Aa = ap[0], Ab = ap[1], ga = gp[0], gb2 = gp[1];
        float A[HID] = {Aa.x, Aa.y, Aa.z, Aa.w, Ab.x, Ab.y, Ab.z, Ab.w};
        float g[HID] = {ga.x, ga.y, ga.z, ga.w, gb2.x, gb2.y, gb2.z, gb2.w};
        float wg[HID];
#pragma unroll
        for (int i = 0; i < HID; i++) wg[i] = win[i] * g[i];
        const float4* xv = (const float4*)(xb + t);
#pragma unroll
        for (int s4 = 0; s4 < 4; s4++) {
            float4 xq = xv[s4];
            float xsv[4] = {xq.x, xq.y, xq.z, xq.w};
#pragma unroll
            for (int s = 0; s < 4; s++) {
#pragma unroll
                for (int i = 0; i < HID; i++)
                    h[i] = fmaf(A[i], h[i], xsv[s] * wg[i]);
                float yv = 0.0f;
#pragma unroll
                for (int i = 0; i < HID; i++) yv = fmaf(h[i], wo[i], yv);
                yb[t + s4 * 4 + s] = yv;
            }
        }
    }
}

extern "C" void kernel_launch(void* const* d_in, const int* in_sizes, int n_in,
                              void* d_out, int out_size) {
    const float* x    = (const float*)d_in[0];
    const float* w_in = (const float*)d_in[1];
    const float* w_out= (const float*)d_in[2];
    const float* w_ih = (const float*)d_in[3];
    const float* w_hh = (const float*)d_in[4];
    const float* b_ih = (const float*)d_in[5];
    const float* b_hh = (const float*)d_in[6];
    const float* w_sl = (const float*)d_in[7];
    const float* b_sl = (const float*)d_in[8];
    float* y = (float*)d_out;

    static int configured = 0;
    if (!configured) {
        cudaFuncSetAttribute(slow_wmma_kernel,
                             cudaFuncAttributeMaxDynamicSharedMemorySize, SM_BYTES);
        configured = 1;
    }

    init_cpar_kernel<<<1, GH>>>(w_ih, b_ih, b_hh);
    slow_wmma_kernel<<<2048, 256, SM_BYTES>>>(x, w_hh, w_sl, b_sl);
    pass1_kernel<<<(BB * NCH) / 256, 256>>>(x, w_in);
    scan_kernel<<<(BB * HID * 32) / 256, 256>>>();
    pass2_kernel<<<(BB * NCH) / 256, 256>>>(x, w_in, w_out, y);
}

// round 11
// speedup vs baseline: 4.9080x; 1.0045x over previous
#include <cuda_runtime.h>
#include <cuda_fp16.h>
#include <mma.h>
#include <math.h>
#include <stdint.h>

using namespace nvcuda;

#define BB   128
#define TT   65536
#define DELTA 16
#define LS   32
#define HID  8
#define GH   64
#define ODIM 16
#define FF   4095
#define CCH  64
#define NCH  (TT/CCH)        // 1024 chunks per batch row

typedef unsigned int u32;

// ---------------- device scratch ----------------
__device__ float d_As[(size_t)BB * FF * HID];
__device__ float d_gs[(size_t)BB * FF * HID];
__device__ float d_P [BB * NCH * HID];
__device__ float d_c [BB * NCH * HID];
__device__ float d_H0[BB * NCH * HID];
__device__ float d_cpar[GH * 8];

__device__ __forceinline__ float sigf(float v) {
    return __fdividef(1.0f, 1.0f + __expf(-v));
}
__device__ __forceinline__ float tanh_f(float v) {
    v = fminf(fmaxf(v, -15.0f), 15.0f);
    float e = __expf(-2.0f * v);
    return __fdividef(1.0f - e, 1.0f + e);
}
__device__ __forceinline__ float tanh_ap(float v) {
    float r; asm("tanh.approx.f32 %0, %1;" : "=f"(r) : "f"(v)); return r;
}
__device__ __forceinline__ float sig_ap(float v) {
    return fmaf(tanh_ap(0.5f * v), 0.5f, 0.5f);
}

__global__ void init_cpar_kernel(const float* __restrict__ w_ih,
                                 const float* __restrict__ b_ih,
                                 const float* __restrict__ b_hh) {
    int j = threadIdx.x;
    if (j < GH) {
        d_cpar[j*8+0] = w_ih[j];
        d_cpar[j*8+1] = w_ih[GH + j];
        d_cpar[j*8+2] = w_ih[2*GH + j];
        d_cpar[j*8+3] = b_ih[j]      + b_hh[j];
        d_cpar[j*8+4] = b_ih[GH + j] + b_hh[GH + j];
        d_cpar[j*8+5] = b_ih[2*GH + j];
        d_cpar[j*8+6] = b_hh[2*GH + j];
        d_cpar[j*8+7] = 0.0f;
    }
}

// ---------------- smem layout (bytes) ----------------
#define LDW   72
#define LDHH  264
#define LDS_X 33
#define SM_WHI  0
#define SM_WLO  (SM_WHI + 192*LDW*2)
#define SM_H    (SM_WLO + 192*LDW*2)
#define SM_XS   (SM_H + 64*LDHH*2)
#define SM_CPAR (SM_XS + 256*LDS_X*4)
#define SM_WSL  (SM_CPAR + GH*8*4)
#define SM_BSL  (SM_WSL + ODIM*GH*4)
#define SM_BYTES (SM_BSL + 64)

// grid = 2048 CTAs, 256 threads. CTA covers frames {2c, 2c+1} x 128 batch rows.
__global__ void __launch_bounds__(256, 1) slow_wmma_kernel(
    const float* __restrict__ x,
    const float* __restrict__ w_hh,
    const float* __restrict__ w_sl,
    const float* __restrict__ b_sl)
{
    extern __shared__ char sm[];
    const int tid  = threadIdx.x;
    const int wid  = tid >> 5;
    const int f0   = blockIdx.x * 2;
    const int cb   = wid * 32;

    __half* WHI = (__half*)(sm + SM_WHI);
    __half* WLO = (__half*)(sm + SM_WLO);
    __half* HS  = (__half*)(sm + SM_H);
    float* xs     = (float*)(sm + SM_XS);
    float* cparsm = (float*)(sm + SM_CPAR);
    float* wslsm  = (float*)(sm + SM_WSL);
    float* bslsm  = (float*)(sm + SM_BSL);

    // ---- probe wmma accumulator element->(row,col) mapping ----
    int jm[8], cm[8];
    {
        __half* pA = (__half*)(sm + SM_XS);
        __half* pB = pA + 256;
        if (tid < 256) {
            int r = tid >> 4, k = tid & 15;
            pA[tid] = __float2half_rn(r == k ? 1.0f : 0.0f);
            pB[tid] = __float2half_rn((float)tid);
        }
        __syncthreads();
        wmma::fragment<wmma::matrix_a, 16,16,16, __half, wmma::row_major> pa;
        wmma::fragment<wmma::matrix_b, 16,16,16, __half, wmma::row_major> pb;
        wmma::fragment<wmma::accumulator, 16,16,16, float> pc;
        wmma::load_matrix_sync(pa, pA, 16);
        wmma::load_matrix_sync(pb, pB, 16);
        wmma::fill_fragment(pc, 0.0f);
        wmma::mma_sync(pc, pa, pb, pc);
#pragma unroll
        for (int e = 0; e < 8; e++) {
            int v = (int)(pc.x[e] + 0.5f);
            jm[e] = v >> 4;
            cm[e] = v & 15;
        }
        __syncthreads();
    }

    // ---- prologue ----
    for (int i = tid; i < 192 * GH; i += 256) {
        int g = i >> 6, k = i & 63;
        float v = w_hh[i];
        __half hi = __float2half_rn(v);
        __half lo = __float2half_rn(v - __half2float(hi));
        WHI[g * LDW + k] = hi;
        WLO[g * LDW + k] = lo;
    }
    for (int i = tid; i < (64 * LDHH * 2) / 4; i += 256)
        ((u32*)(sm + SM_H))[i] = 0u;
    {
        int c = tid;
        int b = c & 127;
        int f = f0 + (c >> 7); if (f > FF - 1) f = FF - 1;
        const float* xp = x + (size_t)b * TT + (size_t)f * DELTA;
#pragma unroll
        for (int t = 0; t < LS; t++) xs[c * LDS_X + t] = xp[t];
    }
    for (int i = tid; i < GH * 8;    i += 256) cparsm[i] = d_cpar[i];
    for (int i = tid; i < ODIM * GH; i += 256) wslsm[i]  = w_sl[i];
    if (tid < ODIM) bslsm[tid] = b_sl[tid];
    __syncthreads();

    // ---- 32 GRU steps ----
#pragma unroll 1
    for (int t = 0; t < LS; t++) {
        float xts[16];
#pragma unroll
        for (int e = 0; e < 8; e++) {
            xts[e]     = xs[(cb + cm[e]) * LDS_X + t];
            xts[8 + e] = xs[(cb + 16 + cm[e]) * LDS_X + t];
        }

        wmma::fragment<wmma::matrix_b, 16,16,16, __half, wmma::row_major> bF[4][2];
#pragma unroll
        for (int kt = 0; kt < 4; kt++)
#pragma unroll
            for (int nt = 0; nt < 2; nt++)
                wmma::load_matrix_sync(bF[kt][nt], HS + (size_t)(kt*16) * LDHH + cb + nt*16, LDHH);

#pragma unroll 1
        for (int mg = 0; mg < 4; mg++) {
            wmma::fragment<wmma::accumulator, 16,16,16, float> acc[3][2];
#pragma unroll
            for (int kind = 0; kind < 3; kind++)
#pragma unroll
                for (int nt = 0; nt < 2; nt++)
                    wmma::fill_fragment(acc[kind][nt], 0.0f);

#pragma unroll
            for (int kind = 0; kind < 3; kind++) {
                const int mi = kind * 4 + mg;
#pragma unroll
                for (int kt = 0; kt < 4; kt++) {
                    wmma::fragment<wmma::matrix_a, 16,16,16, __half, wmma::row_major> aHI, aLO;
                    wmma::load_matrix_sync(aHI, WHI + (size_t)(mi*16) * LDW + kt*16, LDW);
                    wmma::load_matrix_sync(aLO, WLO + (size_t)(mi*16) * LDW + kt*16, LDW);
                    wmma::mma_sync(acc[kind][0], aHI, bF[kt][0], acc[kind][0]);
                    wmma::mma_sync(acc[kind][1], aHI, bF[kt][1], acc[kind][1]);
                    wmma::mma_sync(acc[kind][0], aLO, bF[kt][0], acc[kind][0]);
                    wmma::mma_sync(acc[kind][1], aLO, bF[kt][1], acc[kind][1]);
                }
            }

            // fragment-direct epilogue; r,z sigmoids via tanh.approx (MUFU cut)
#pragma unroll
            for (int e = 0; e < 8; e++) {
                const int j = mg * 16 + jm[e];
                const float4 c0 = ((const float4*)(cparsm + j * 8))[0];
                const float4 c1 = ((const float4*)(cparsm + j * 8))[1];
#pragma unroll
                for (int nt = 0; nt < 2; nt++) {
                    const int c = cb + nt * 16 + cm[e];
                    const float xt = xts[nt * 8 + e];
                    float gr = acc[0][nt].x[e];
                    float gz = acc[1][nt].x[e];
                    float gn = acc[2][nt].x[e];

                    float ho = __half2float(HS[(size_t)j * LDHH + c]);

                    float r = sig_ap(gr + fmaf(xt, c0.x, c0.w));
                    float z = sig_ap(gz + fmaf(xt, c0.y, c1.x));
                    float n = tanh_f(fmaf(xt, c0.z, c1.y) + r * (gn + c1.z));
                    float h = n + z * (ho - n);

                    HS[(size_t)j * LDHH + c] = __float2half_rn(h);
                }
            }
        }
        __syncwarp();
    }

    // ---- final projection (accurate sigmoid) ----
    {
        const int c = tid;
        const int b = c & 127;
        const int f = f0 + (c >> 7);
        if (f < FF) {
            float hv[GH];
#pragma unroll
            for (int k = 0; k < GH; k++)
                hv[k] = __half2float(HS[(size_t)k * LDHH + c]);
            const size_t ob = ((size_t)b * FF + f) * HID;
#pragma unroll 1
            for (int o = 0; o < HID; o++) {
                float a0 = bslsm[o];
                float a1 = bslsm[HID + o];
#pragma unroll
                for (int k = 0; k < GH; k++) {
                    a0 = fmaf(wslsm[o * GH + k], hv[k], a0);
                    a1 = fmaf(wslsm[(HID + o) * GH + k], hv[k], a1);
                }
                d_As[ob + o] = sigf(a0);
                d_gs[ob + o] = a1;
            }
        }
    }
}

// ---------------- fast branch ----------------
__global__ void __launch_bounds__(256) pass1_kernel(
    const float* __restrict__ x, const float* __restrict__ w_in)
{
    int q = blockIdx.x * blockDim.x + threadIdx.x;
    if (q >= BB * NCH) return;
    int b = q / NCH, ch = q % NCH;
    float win[HID], P[HID], c[HID];
#pragma unroll
    for (int i = 0; i < HID; i++) { win[i] = w_in[i]; P[i] = 1.0f; c[i] = 0.0f; }
    const int t0 = ch * CCH;
    const float* xb = x + (size_t)b * TT;
#pragma unroll 1
    for (int blk = 0; blk < CCH / 16; blk++) {
        int t = t0 + blk * 16;
        int j = (t >> 4) - 1; if (j < 0) j = 0;
        const float4* ap = (const float4*)(d_As + ((size_t)b * FF + j) * HID);
        const float4* gp = (const float4*)(d_gs + ((size_t)b * FF + j) * HID);
        float4 Aa = ap[0], Ab = ap[1], ga = gp[0], gb2 = gp[1];
        float A[HID] = {Aa.x, Aa.y, Aa.z, Aa.w, Ab.x, Ab.y, Ab.z, Ab.w};
        float g[HID] = {ga.x, ga.y, ga.z, ga.w, gb2.x, gb2.y, gb2.z, gb2.w};
        float wg[HID], a16[HID];
#pragma unroll
        for (int i = 0; i < HID; i++) {
            wg[i] = win[i] * g[i];
            float a2 = A[i]*A[i], a4 = a2*a2, a8 = a4*a4;
            a16[i] = a8*a8;
        }
        const float4* xv = (const float4*)(xb + t);
#pragma unroll
        for (int s4 = 0; s4 < 4; s4++) {
            float4 xq = xv[s4];
            float xsv[4] = {xq.x, xq.y, xq.z, xq.w};
#pragma unroll
            for (int s = 0; s < 4; s++)
#pragma unroll
                for (int i = 0; i < HID; i++)
                    c[i] = fmaf(A[i], c[i], xsv[s] * wg[i]);
        }
#pragma unroll
        for (int i = 0; i < HID; i++) P[i] *= a16[i];
    }
    const size_t base = ((size_t)b * NCH + ch) * HID;
#pragma unroll
    for (int i = 0; i < HID; i++) { d_P[base + i] = P[i]; d_c[base + i] = c[i]; }
}

// 1024 (b,i) chains; one warp per chain; lane owns 32 consecutive chunks.
__global__ void __launch_bounds__(256) scan_kernel() {
    int gw   = (blockIdx.x * blockDim.x + threadIdx.x) >> 5;
    int lane = threadIdx.x & 31;
    int b = gw >> 3, i = gw & 7;
    const int S = NCH / 32;   // 32 chunks per lane
    float P[S], c[S];
#pragma unroll
    for (int s = 0; s < S; s++) {
        size_t idx = ((size_t)b * NCH + (lane * S + s)) * HID + i;
        P[s] = d_P[idx]; c[s] = d_c[idx];
    }
    float Pt = 1.0f, ct = 0.0f;
#pragma unroll
    for (int s = 0; s < S; s++) { ct = fmaf(P[s], ct, c[s]); Pt *= P[s]; }
#pragma unroll
    for (int off = 1; off < 32; off <<= 1) {
        float Pp = __shfl_up_sync(0xffffffffu, Pt, off);
        float cp = __shfl_up_sync(0xffffffffu, ct, off);
        if (lane >= off) { ct = fmaf(Pt, cp, ct); Pt *= Pp; }
    }
    float h = __shfl_up_sync(0xffffffffu, ct, 1);
    if (lane == 0) h = 0.0f;
#pragma unroll
    for (int s = 0; s < S; s++) {
        size_t idx = ((size_t)b * NCH + (lane * S + s)) * HID + i;
        d_H0[idx] = h;
        h = fmaf(P[s], h, c[s]);
    }
}

__global__ void __launch_bounds__(256) pass2_kernel(
    const float* __restrict__ x, const float* __restrict__ w_in,
    const float* __restrict__ w_out, float* __restrict__ y)
{
    int q = blockIdx.x * blockDim.x + threadIdx.x;
    if (q >= BB * NCH) return;
    int b = q / NCH, ch = q % NCH;
    float win[HID], wo[HID], h[HID];
#pragma unroll
    for (int i = 0; i < HID; i++) {
        win[i] = w_in[i]; wo[i] = w_out[i];
        h[i] = d_H0[((size_t)b * NCH + ch) * HID + i];
    }
    const int t0 = ch * CCH;
    const float* xb = x + (size_t)b * TT;
    float* yb = y + (size_t)b * TT;
#pragma unroll 1
    for (int blk = 0; blk < CCH / 16; blk++) {
        int t = t0 + blk * 16;
        int j = (t >> 4) - 1; if (j < 0) j = 0;
        const float4* ap = (const float4*)(d_As + ((size_t)b * FF + j) * HID);
        const float4* gp = (const float4*)(d_gs + ((size_t)b * FF + j) * HID);
        float4 Aa = ap[0], Ab = ap[1], ga = gp[0], gb2 = gp[1];
        float A[HID] = {Aa.x, Aa.y, Aa.z, Aa.w, Ab.x, Ab.y, Ab.z, Ab.w};
        float g[HID] = {ga.x, ga.y, ga.z, ga.w, gb2.x, gb2.y, gb2.z, gb2.w};
        float wg[HID];
#pragma unroll
        for (int i = 0; i < HID; i++) wg[i] = win[i] * g[i];
        const float4* xv = (const float4*)(xb + t);
#pragma unroll
        for (int s4 = 0; s4 < 4; s4++) {
            float4 xq = xv[s4];
            float xsv[4] = {xq.x, xq.y, xq.z, xq.w};
#pragma unroll
            for (int s = 0; s < 4; s++) {
#pragma unroll
                for (int i = 0; i < HID; i++)
                    h[i] = fmaf(A[i], h[i], xsv[s] * wg[i]);
                float yv = 0.0f;
#pragma unroll
                for (int i = 0; i < HID; i++) yv = fmaf(h[i], wo[i], yv);
                yb[t + s4 * 4 + s] = yv;
            }
        }
    }
}

extern "C" void kernel_launch(void* const* d_in, const int* in_sizes, int n_in,
                              void* d_out, int out_size) {
    const float* x    = (const float*)d_in[0];
    const float* w_in = (const float*)d_in[1];
    const float* w_out= (const float*)d_in[2];
    const float* w_ih = (const float*)d_in[3];
    const float* w_hh = (const float*)d_in[4];
    const float* b_ih = (const float*)d_in[5];
    const float* b_hh = (const float*)d_in[6];
    const float* w_sl = (const float*)d_in[7];
    const float* b_sl = (const float*)d_in[8];
    float* y = (float*)d_out;

    static int configured = 0;
    if (!configured) {
        cudaFuncSetAttribute(slow_wmma_kernel,
                             cudaFuncAttributeMaxDynamicSharedMemorySize, SM_BYTES);
        configured = 1;
    }

    init_cpar_kernel<<<1, GH>>>(w_ih, b_ih, b_hh);
    slow_wmma_kernel<<<2048, 256, SM_BYTES>>>(x, w_hh, w_sl, b_sl);
    pass1_kernel<<<(BB * NCH) / 256, 256>>>(x, w_in);
    scan_kernel<<<(BB * HID * 32) / 256, 256>>>();
    pass2_kernel<<<(BB * NCH) / 256, 256>>>(x, w_in, w_out, y);
}

// round 12
// speedup vs baseline: 7.4764x; 1.5233x over previous
#include <cuda_runtime.h>
#include <cuda_fp16.h>
#include <mma.h>
#include <math.h>
#include <stdint.h>

using namespace nvcuda;

#define BB   128
#define TT   65536
#define DELTA 16
#define LS   32
#define HID  8
#define GH   64
#define ODIM 16
#define FF   4095
#define CCH  64
#define NCH  (TT/CCH)

typedef unsigned int u32;

// ---------------- device scratch ----------------
__device__ float d_As[(size_t)BB * FF * HID];
__device__ float d_gs[(size_t)BB * FF * HID];
__device__ float d_P [BB * NCH * HID];
__device__ float d_c [BB * NCH * HID];
__device__ float d_H0[BB * NCH * HID];
__device__ float d_cpar[GH * 8];

__device__ __forceinline__ float sigf(float v) {
    return __fdividef(1.0f, 1.0f + __expf(-v));
}
__device__ __forceinline__ float tanh_ap(float v) {
    float r; asm("tanh.approx.f32 %0, %1;" : "=f"(r) : "f"(v)); return r;
}
__device__ __forceinline__ float sig_ap(float v) {
    return fmaf(tanh_ap(0.5f * v), 0.5f, 0.5f);
}

__global__ void init_cpar_kernel(const float* __restrict__ w_ih,
                                 const float* __restrict__ b_ih,
                                 const float* __restrict__ b_hh) {
    int j = threadIdx.x;
    if (j < GH) {
        d_cpar[j*8+0] = w_ih[j];
        d_cpar[j*8+1] = w_ih[GH + j];
        d_cpar[j*8+2] = w_ih[2*GH + j];
        d_cpar[j*8+3] = b_ih[j]      + b_hh[j];
        d_cpar[j*8+4] = b_ih[GH + j] + b_hh[GH + j];
        d_cpar[j*8+5] = b_ih[2*GH + j];
        d_cpar[j*8+6] = b_hh[2*GH + j];
        d_cpar[j*8+7] = 0.0f;
    }
}

// ---------------- smem layout (bytes) ----------------
#define LDW   72
#define LDHH  264
#define LDS_X 33
#define SM_WHI  0
#define SM_WLO  (SM_WHI + 192*LDW*2)
#define SM_H    (SM_WLO + 192*LDW*2)
#define SM_XS   (SM_H + 64*LDHH*2)
#define SM_CPAR (SM_XS + 256*LDS_X*4)
#define SM_WSL  (SM_CPAR + GH*8*4)
#define SM_BSL  (SM_WSL + ODIM*GH*4)
#define SM_BYTES (SM_BSL + 64)

// grid = 2048 CTAs, 256 threads. CTA covers frames {2c, 2c+1} x 128 batch rows.
__global__ void __launch_bounds__(256, 1) slow_wmma_kernel(
    const float* __restrict__ x,
    const float* __restrict__ w_hh,
    const float* __restrict__ w_sl,
    const float* __restrict__ b_sl)
{
    extern __shared__ char sm[];
    const int tid  = threadIdx.x;
    const int wid  = tid >> 5;
    const int f0   = blockIdx.x * 2;
    const int cb   = wid * 32;

    __half* WHI = (__half*)(sm + SM_WHI);
    __half* WLO = (__half*)(sm + SM_WLO);
    __half* HS  = (__half*)(sm + SM_H);
    float* xs     = (float*)(sm + SM_XS);
    float* cparsm = (float*)(sm + SM_CPAR);
    float* wslsm  = (float*)(sm + SM_WSL);
    float* bslsm  = (float*)(sm + SM_BSL);

    // ---- probe wmma accumulator element->(row,col) mapping ----
    int jm[8], cm[8];
    {
        __half* pA = (__half*)(sm + SM_XS);
        __half* pB = pA + 256;
        if (tid < 256) {
            int r = tid >> 4, k = tid & 15;
            pA[tid] = __float2half_rn(r == k ? 1.0f : 0.0f);
            pB[tid] = __float2half_rn((float)tid);
        }
        __syncthreads();
        wmma::fragment<wmma::matrix_a, 16,16,16, __half, wmma::row_major> pa;
        wmma::fragment<wmma::matrix_b, 16,16,16, __half, wmma::row_major> pb;
        wmma::fragment<wmma::accumulator, 16,16,16, float> pc;
        wmma::load_matrix_sync(pa, pA, 16);
        wmma::load_matrix_sync(pb, pB, 16);
        wmma::fill_fragment(pc, 0.0f);
        wmma::mma_sync(pc, pa, pb, pc);
#pragma unroll
        for (int e = 0; e < 8; e++) {
            int v = (int)(pc.x[e] + 0.5f);
            jm[e] = v >> 4;
            cm[e] = v & 15;
        }
        __syncthreads();
    }

    // ---- prologue ----
    for (int i = tid; i < 192 * GH; i += 256) {
        int g = i >> 6, k = i & 63;
        float v = w_hh[i];
        __half hi = __float2half_rn(v);
        __half lo = __float2half_rn(v - __half2float(hi));
        WHI[g * LDW + k] = hi;
        WLO[g * LDW + k] = lo;
    }
    for (int i = tid; i < (64 * LDHH * 2) / 4; i += 256)
        ((u32*)(sm + SM_H))[i] = 0u;
    {
        int c = tid;
        int b = c & 127;
        int f = f0 + (c >> 7); if (f > FF - 1) f = FF - 1;
        const float* xp = x + (size_t)b * TT + (size_t)f * DELTA;
#pragma unroll
        for (int t = 0; t < LS; t++) xs[c * LDS_X + t] = xp[t];
    }
    for (int i = tid; i < GH * 8;    i += 256) cparsm[i] = d_cpar[i];
    for (int i = tid; i < ODIM * GH; i += 256) wslsm[i]  = w_sl[i];
    if (tid < ODIM) bslsm[tid] = b_sl[tid];
    __syncthreads();

    // ---- 32 GRU steps ----
#pragma unroll 1
    for (int t = 0; t < LS; t++) {
        float xts[16];
#pragma unroll
        for (int e = 0; e < 8; e++) {
            xts[e]     = xs[(cb + cm[e]) * LDS_X + t];
            xts[8 + e] = xs[(cb + 16 + cm[e]) * LDS_X + t];
        }

        wmma::fragment<wmma::matrix_b, 16,16,16, __half, wmma::row_major> bF[4][2];
#pragma unroll
        for (int kt = 0; kt < 4; kt++)
#pragma unroll
            for (int nt = 0; nt < 2; nt++)
                wmma::load_matrix_sync(bF[kt][nt], HS + (size_t)(kt*16) * LDHH + cb + nt*16, LDHH);

#pragma unroll 1
        for (int mg = 0; mg < 4; mg++) {
            wmma::fragment<wmma::accumulator, 16,16,16, float> acc[3][2];
#pragma unroll
            for (int kind = 0; kind < 3; kind++)
#pragma unroll
                for (int nt = 0; nt < 2; nt++)
                    wmma::fill_fragment(acc[kind][nt], 0.0f);

            // r,z gates: hi product only (W-quant error damped by sigmoid');
            // n gate: hi + lo (sensitive path keeps split precision)
#pragma unroll
            for (int kind = 0; kind < 3; kind++) {
                const int mi = kind * 4 + mg;
#pragma unroll
                for (int kt = 0; kt < 4; kt++) {
                    wmma::fragment<wmma::matrix_a, 16,16,16, __half, wmma::row_major> aHI;
                    wmma::load_matrix_sync(aHI, WHI + (size_t)(mi*16) * LDW + kt*16, LDW);
                    wmma::mma_sync(acc[kind][0], aHI, bF[kt][0], acc[kind][0]);
                    wmma::mma_sync(acc[kind][1], aHI, bF[kt][1], acc[kind][1]);
                    if (kind == 2) {
                        wmma::fragment<wmma::matrix_a, 16,16,16, __half, wmma::row_major> aLO;
                        wmma::load_matrix_sync(aLO, WLO + (size_t)(mi*16) * LDW + kt*16, LDW);
                        wmma::mma_sync(acc[2][0], aLO, bF[kt][0], acc[2][0]);
                        wmma::mma_sync(acc[2][1], aLO, bF[kt][1], acc[2][1]);
                    }
                }
            }

            // fragment-direct epilogue; all nonlinearities via MUFU.TANH
#pragma unroll
            for (int e = 0; e < 8; e++) {
                const int j = mg * 16 + jm[e];
                const float4 c0 = ((const float4*)(cparsm + j * 8))[0];
                const float4 c1 = ((const float4*)(cparsm + j * 8))[1];
#pragma unroll
                for (int nt = 0; nt < 2; nt++) {
                    const int c = cb + nt * 16 + cm[e];
                    const float xt = xts[nt * 8 + e];
                    float gr = acc[0][nt].x[e];
                    float gz = acc[1][nt].x[e];
                    float gn = acc[2][nt].x[e];

                    float ho = __half2float(HS[(size_t)j * LDHH + c]);

                    float r = sig_ap(gr + fmaf(xt, c0.x, c0.w));
                    float z = sig_ap(gz + fmaf(xt, c0.y, c1.x));
                    float n = tanh_ap(fmaf(xt, c0.z, c1.y) + r * (gn + c1.z));
                    float h = n + z * (ho - n);

                    HS[(size_t)j * LDHH + c] = __float2half_rn(h);
                }
            }
        }
        __syncwarp();
    }

    // ---- final projection (accurate sigmoid) ----
    {
        const int c = tid;
        const int b = c & 127;
        const int f = f0 + (c >> 7);
        if (f < FF) {
            float hv[GH];
#pragma unroll
            for (int k = 0; k < GH; k++)
                hv[k] = __half2float(HS[(size_t)k * LDHH + c]);
            const size_t ob = ((size_t)b * FF + f) * HID;
#pragma unroll 1
            for (int o = 0; o < HID; o++) {
                float a0 = bslsm[o];
                float a1 = bslsm[HID + o];
#pragma unroll
                for (int k = 0; k < GH; k++) {
                    a0 = fmaf(wslsm[o * GH + k], hv[k], a0);
                    a1 = fmaf(wslsm[(HID + o) * GH + k], hv[k], a1);
                }
                d_As[ob + o] = sigf(a0);
                d_gs[ob + o] = a1;
            }
        }
    }
}

// ---------------- fast branch ----------------
__global__ void __launch_bounds__(256) pass1_kernel(
    const float* __restrict__ x, const float* __restrict__ w_in)
{
    int q = blockIdx.x * blockDim.x + threadIdx.x;
    if (q >= BB * NCH) return;
    int b = q / NCH, ch = q % NCH;
    float win[HID], P[HID], c[HID];
#pragma unroll
    for (int i = 0; i < HID; i++) { win[i] = w_in[i]; P[i] = 1.0f; c[i] = 0.0f; }
    const int t0 = ch * CCH;
    const float* xb = x + (size_t)b * TT;
#pragma unroll 1
    for (int blk = 0; blk < CCH / 16; blk++) {
        int t = t0 + blk * 16;
        int j = (t >> 4) - 1; if (j < 0) j = 0;
        const float4* ap = (const float4*)(d_As + ((size_t)b * FF + j) * HID);
        const float4* gp = (const float4*)(d_gs + ((size_t)b * FF + j) * HID);
        float4 Aa = ap[0], Ab = ap[1], ga = gp[0], gb2 = gp[1];
        float A[HID] = {Aa.x, Aa.y, Aa.z, Aa.w, Ab.x, Ab.y, Ab.z, Ab.w};
        float g[HID] = {ga.x, ga.y, ga.z, ga.w, gb2.x, gb2.y, gb2.z, gb2.w};
        float wg[HID], a16[HID];
#pragma unroll
        for (int i = 0; i < HID; i++) {
            wg[i] = win[i] * g[i];
            float a2 = A[i]*A[i], a4 = a2*a2, a8 = a4*a4;
            a16[i] = a8*a8;
        }
        const float4* xv = (const float4*)(xb + t);
#pragma unroll
        for (int s4 = 0; s4 < 4; s4++) {
            float4 xq = xv[s4];
            float xsv[4] = {xq.x, xq.y, xq.z, xq.w};
#pragma unroll
            for (int s = 0; s < 4; s++)
#pragma unroll
                for (int i = 0; i < HID; i++)
                    c[i] = fmaf(A[i], c[i], xsv[s] * wg[i]);
        }
#pragma unroll
        for (int i = 0; i < HID; i++) P[i] *= a16[i];
    }
    const size_t base = ((size_t)b * NCH + ch) * HID;
#pragma unroll
    for (int i = 0; i < HID; i++) { d_P[base + i] = P[i]; d_c[base + i] = c[i]; }
}

__global__ void __launch_bounds__(256) scan_kernel() {
    int gw   = (blockIdx.x * blockDim.x + threadIdx.x) >> 5;
    int lane = threadIdx.x & 31;
    int b = gw >> 3, i = gw & 7;
    const int S = NCH / 32;
    float P[S], c[S];
#pragma unroll
    for (int s = 0; s < S; s++) {
        size_t idx = ((size_t)b * NCH + (lane * S + s)) * HID + i;
        P[s] = d_P[idx]; c[s] = d_c[idx];
    }
    float Pt = 1.0f, ct = 0.0f;
#pragma unroll
    for (int s = 0; s < S; s++) { ct = fmaf(P[s], ct, c[s]); Pt *= P[s]; }
#pragma unroll
    for (int off = 1; off < 32; off <<= 1) {
        float Pp = __shfl_up_sync(0xffffffffu, Pt, off);
        float cp = __shfl_up_sync(0xffffffffu, ct, off);
        if (lane >= off) { ct = fmaf(Pt, cp, ct); Pt *= Pp; }
    }
    float h = __shfl_up_sync(0xffffffffu, ct, 1);
    if (lane == 0) h = 0.0f;
#pragma unroll
    for (int s = 0; s < S; s++) {
        size_t idx = ((size_t)b * NCH + (lane * S + s)) * HID + i;
        d_H0[idx] = h;
        h = fmaf(P[s], h, c[s]);
    }
}

__global__ void __launch_bounds__(256) pass2_kernel(
    const float* __restrict__ x, const float* __restrict__ w_in,
    const float* __restrict__ w_out, float* __restrict__ y)
{
    int q = blockIdx.x * blockDim.x + threadIdx.x;
    if (q >= BB * NCH) return;
    int b = q / NCH, ch = q % NCH;
    float win[HID], wo[HID], h[HID];
#pragma unroll
    for (int i = 0; i < HID; i++) {
        win[i] = w_in[i]; wo[i] = w_out[i];
        h[i] = d_H0[((size_t)b * NCH + ch) * HID + i];
    }
    const int t0 = ch * CCH;
    const float* xb = x + (size_t)b * TT;
    float* yb = y + (size_t)b * TT;
#pragma unroll 1
    for (int blk = 0; blk < CCH / 16; blk++) {
        int t = t0 + blk * 16;
        int j = (t >> 4) - 1; if (j < 0) j = 0;
        const float4* ap = (const float4*)(d_As + ((size_t)b * FF + j) * HID);
        const float4* gp = (const float4*)(d_gs + ((size_t)b * FF + j) * HID);
        float4 Aa = ap[0], Ab = ap[1], ga = gp[0], gb2 = gp[1];
        float A[HID] = {Aa.x, Aa.y, Aa.z, Aa.w, Ab.x, Ab.y, Ab.z, Ab.w};
        float g[HID] = {ga.x, ga.y, ga.z, ga.w, gb2.x, gb2.y, gb2.z, gb2.w};
        float wg[HID];
#pragma unroll
        for (int i = 0; i < HID; i++) wg[i] = win[i] * g[i];
        const float4* xv = (const float4*)(xb + t);
#pragma unroll
        for (int s4 = 0; s4 < 4; s4++) {
            float4 xq = xv[s4];
            float xsv[4] = {xq.x, xq.y, xq.z, xq.w};
#pragma unroll
            for (int s = 0; s < 4; s++) {
#pragma unroll
                for (int i = 0; i < HID; i++)
                    h[i] = fmaf(A[i], h[i], xsv[s] * wg[i]);
                float yv = 0.0f;
#pragma unroll
                for (int i = 0; i < HID; i++) yv = fmaf(h[i], wo[i], yv);
                yb[t + s4 * 4 + s] = yv;
            }
        }
    }
}

extern "C" void kernel_launch(void* const* d_in, const int* in_sizes, int n_in,
                              void* d_out, int out_size) {
    const float* x    = (const float*)d_in[0];
    const float* w_in = (const float*)d_in[1];
    const float* w_out= (const float*)d_in[2];
    const float* w_ih = (const float*)d_in[3];
    const float* w_hh = (const float*)d_in[4];
    const float* b_ih = (const float*)d_in[5];
    const float* b_hh = (const float*)d_in[6];
    const float* w_sl = (const float*)d_in[7];
    const float* b_sl = (const float*)d_in[8];
    float* y = (float*)d_out;

    static int configured = 0;
    if (!configured) {
        cudaFuncSetAttribute(slow_wmma_kernel,
                             cudaFuncAttributeMaxDynamicSharedMemorySize, SM_BYTES);
        configured = 1;
    }

    init_cpar_kernel<<<1, GH>>>(w_ih, b_ih, b_hh);
    slow_wmma_kernel<<<2048, 256, SM_BYTES>>>(x, w_hh, w_sl, b_sl);
    pass1_kernel<<<(BB * NCH) / 256, 256>>>(x, w_in);
    scan_kernel<<<(BB * HID * 32) / 256, 256>>>();
    pass2_kernel<<<(BB * NCH) / 256, 256>>>(x, w_in, w_out, y);
}

// round 13
// speedup vs baseline: 7.5154x; 1.0052x over previous
#include <cuda_runtime.h>
#include <cuda_fp16.h>
#include <mma.h>
#include <math.h>
#include <stdint.h>

using namespace nvcuda;

#define BB   128
#define TT   65536
#define DELTA 16
#define LS   32
#define HID  8
#define GH   64
#define ODIM 16
#define FF   4095
#define CCH  64
#define NCH  (TT/CCH)

typedef unsigned int u32;

// ---------------- device scratch ----------------
__device__ float d_As[(size_t)BB * FF * HID];
__device__ float d_gs[(size_t)BB * FF * HID];
__device__ float d_P [BB * NCH * HID];
__device__ float d_c [BB * NCH * HID];
__device__ float d_H0[BB * NCH * HID];
__device__ float d_cpar[GH * 8];

__device__ __forceinline__ float sigf(float v) {
    return __fdividef(1.0f, 1.0f + __expf(-v));
}
__device__ __forceinline__ float tanh_ap(float v) {
    float r; asm("tanh.approx.f32 %0, %1;" : "=f"(r) : "f"(v)); return r;
}
__device__ __forceinline__ float sig_ap(float v) {
    return fmaf(tanh_ap(0.5f * v), 0.5f, 0.5f);
}

__global__ void init_cpar_kernel(const float* __restrict__ w_ih,
                                 const float* __restrict__ b_ih,
                                 const float* __restrict__ b_hh) {
    int j = threadIdx.x;
    if (j < GH) {
        d_cpar[j*8+0] = w_ih[j];
        d_cpar[j*8+1] = w_ih[GH + j];
        d_cpar[j*8+2] = w_ih[2*GH + j];
        d_cpar[j*8+3] = b_ih[j]      + b_hh[j];
        d_cpar[j*8+4] = b_ih[GH + j] + b_hh[GH + j];
        d_cpar[j*8+5] = b_ih[2*GH + j];
        d_cpar[j*8+6] = b_hh[2*GH + j];
        d_cpar[j*8+7] = 0.0f;
    }
}

// ---------------- smem layout (bytes) ----------------
#define LDW   72
#define LDHH  264
#define LDS_X 33
#define SM_WHI  0
#define SM_H    (SM_WHI + 192*LDW*2)         // 27648
#define SM_XS   (SM_H + 64*LDHH*2)           // 61440
#define SM_CPAR (SM_XS + 256*LDS_X*4)        // 95232
#define SM_WSL  (SM_CPAR + GH*8*4)
#define SM_BSL  (SM_WSL + ODIM*GH*4)
#define SM_BYTES (SM_BSL + 64)

// grid = 2048 CTAs, 256 threads. CTA covers frames {2c, 2c+1} x 128 batch rows.
__global__ void __launch_bounds__(256, 1) slow_wmma_kernel(
    const float* __restrict__ x,
    const float* __restrict__ w_hh,
    const float* __restrict__ w_sl,
    const float* __restrict__ b_sl)
{
    extern __shared__ char sm[];
    const int tid  = threadIdx.x;
    const int wid  = tid >> 5;
    const int f0   = blockIdx.x * 2;
    const int cb   = wid * 32;

    __half* WHI = (__half*)(sm + SM_WHI);
    __half* HS  = (__half*)(sm + SM_H);
    float* xs     = (float*)(sm + SM_XS);
    float* cparsm = (float*)(sm + SM_CPAR);
    float* wslsm  = (float*)(sm + SM_WSL);
    float* bslsm  = (float*)(sm + SM_BSL);

    // ---- probe wmma accumulator element->(row,col) mapping ----
    int jm[8], cm[8];
    {
        __half* pA = (__half*)(sm + SM_XS);
        __half* pB = pA + 256;
        if (tid < 256) {
            int r = tid >> 4, k = tid & 15;
            pA[tid] = __float2half_rn(r == k ? 1.0f : 0.0f);
            pB[tid] = __float2half_rn((float)tid);
        }
        __syncthreads();
        wmma::fragment<wmma::matrix_a, 16,16,16, __half, wmma::row_major> pa;
        wmma::fragment<wmma::matrix_b, 16,16,16, __half, wmma::row_major> pb;
        wmma::fragment<wmma::accumulator, 16,16,16, float> pc;
        wmma::load_matrix_sync(pa, pA, 16);
        wmma::load_matrix_sync(pb, pB, 16);
        wmma::fill_fragment(pc, 0.0f);
        wmma::mma_sync(pc, pa, pb, pc);
#pragma unroll
        for (int e = 0; e < 8; e++) {
            int v = (int)(pc.x[e] + 0.5f);
            jm[e] = v >> 4;
            cm[e] = v & 15;
        }
        __syncthreads();
    }

    // ---- prologue ----
    for (int i = tid; i < 192 * GH; i += 256) {
        int g = i >> 6, k = i & 63;
        WHI[g * LDW + k] = __float2half_rn(w_hh[i]);
    }
    for (int i = tid; i < (64 * LDHH * 2) / 4; i += 256)
        ((u32*)(sm + SM_H))[i] = 0u;
    {
        int c = tid;
        int b = c & 127;
        int f = f0 + (c >> 7); if (f > FF - 1) f = FF - 1;
        const float* xp = x + (size_t)b * TT + (size_t)f * DELTA;
#pragma unroll
        for (int t = 0; t < LS; t++) xs[c * LDS_X + t] = xp[t];
    }
    for (int i = tid; i < GH * 8;    i += 256) cparsm[i] = d_cpar[i];
    for (int i = tid; i < ODIM * GH; i += 256) wslsm[i]  = w_sl[i];
    if (tid < ODIM) bslsm[tid] = b_sl[tid];
    __syncthreads();

    // ---- 32 GRU steps ----
#pragma unroll 1
    for (int t = 0; t < LS; t++) {
        float xts[16];
#pragma unroll
        for (int e = 0; e < 8; e++) {
            xts[e]     = xs[(cb + cm[e]) * LDS_X + t];
            xts[8 + e] = xs[(cb + 16 + cm[e]) * LDS_X + t];
        }

        wmma::fragment<wmma::matrix_b, 16,16,16, __half, wmma::row_major> bF[4][2];
#pragma unroll
        for (int kt = 0; kt < 4; kt++)
#pragma unroll
            for (int nt = 0; nt < 2; nt++)
                wmma::load_matrix_sync(bF[kt][nt], HS + (size_t)(kt*16) * LDHH + cb + nt*16, LDHH);

#pragma unroll 1
        for (int mg = 0; mg < 4; mg++) {
            wmma::fragment<wmma::accumulator, 16,16,16, float> acc[3][2];
#pragma unroll
            for (int kind = 0; kind < 3; kind++)
#pragma unroll
                for (int nt = 0; nt < 2; nt++)
                    wmma::fill_fragment(acc[kind][nt], 0.0f);

            // hi-only W for all gates (fp16 W-quant error is contractive, ~4.4e-4 total)
#pragma unroll
            for (int kind = 0; kind < 3; kind++) {
                const int mi = kind * 4 + mg;
#pragma unroll
                for (int kt = 0; kt < 4; kt++) {
                    wmma::fragment<wmma::matrix_a, 16,16,16, __half, wmma::row_major> aHI;
                    wmma::load_matrix_sync(aHI, WHI + (size_t)(mi*16) * LDW + kt*16, LDW);
                    wmma::mma_sync(acc[kind][0], aHI, bF[kt][0], acc[kind][0]);
                    wmma::mma_sync(acc[kind][1], aHI, bF[kt][1], acc[kind][1]);
                }
            }

            // fragment-direct epilogue; all nonlinearities via MUFU.TANH
#pragma unroll
            for (int e = 0; e < 8; e++) {
                const int j = mg * 16 + jm[e];
                const float4 c0 = ((const float4*)(cparsm + j * 8))[0];
                const float4 c1 = ((const float4*)(cparsm + j * 8))[1];
#pragma unroll
                for (int nt = 0; nt < 2; nt++) {
                    const int c = cb + nt * 16 + cm[e];
                    const float xt = xts[nt * 8 + e];
                    float gr = acc[0][nt].x[e];
                    float gz = acc[1][nt].x[e];
                    float gn = acc[2][nt].x[e];

                    float ho = __half2float(HS[(size_t)j * LDHH + c]);

                    float r = sig_ap(gr + fmaf(xt, c0.x, c0.w));
                    float z = sig_ap(gz + fmaf(xt, c0.y, c1.x));
                    float n = tanh_ap(fmaf(xt, c0.z, c1.y) + r * (gn + c1.z));
                    float h = n + z * (ho - n);

                    HS[(size_t)j * LDHH + c] = __float2half_rn(h);
                }
            }
        }
        __syncwarp();
    }

    // ---- final projection (accurate sigmoid) ----
    {
        const int c = tid;
        const int b = c & 127;
        const int f = f0 + (c >> 7);
        if (f < FF) {
            float hv[GH];
#pragma unroll
            for (int k = 0; k < GH; k++)
                hv[k] = __half2float(HS[(size_t)k * LDHH + c]);
            const size_t ob = ((size_t)b * FF + f) * HID;
#pragma unroll 1
            for (int o = 0; o < HID; o++) {
                float a0 = bslsm[o];
                float a1 = bslsm[HID + o];
#pragma unroll
                for (int k = 0; k < GH; k++) {
                    a0 = fmaf(wslsm[o * GH + k], hv[k], a0);
                    a1 = fmaf(wslsm[(HID + o) * GH + k], hv[k], a1);
                }
                d_As[ob + o] = sigf(a0);
                d_gs[ob + o] = a1;
            }
        }
    }
}

// ---------------- fast branch ----------------
__global__ void __launch_bounds__(256) pass1_kernel(
    const float* __restrict__ x, const float* __restrict__ w_in)
{
    int q = blockIdx.x * blockDim.x + threadIdx.x;
    if (q >= BB * NCH) return;
    int b = q / NCH, ch = q % NCH;
    float win[HID], P[HID], c[HID];
#pragma unroll
    for (int i = 0; i < HID; i++) { win[i] = w_in[i]; P[i] = 1.0f; c[i] = 0.0f; }
    const int t0 = ch * CCH;
    const float* xb = x + (size_t)b * TT;
#pragma unroll 1
    for (int blk = 0; blk < CCH / 16; blk++) {
        int t = t0 + blk * 16;
        int j = (t >> 4) - 1; if (j < 0) j = 0;
        const float4* ap = (const float4*)(d_As + ((size_t)b * FF + j) * HID);
        const float4* gp = (const float4*)(d_gs + ((size_t)b * FF + j) * HID);
        float4 Aa = ap[0], Ab = ap[1], ga = gp[0], gb2 = gp[1];
        float A[HID] = {Aa.x, Aa.y, Aa.z, Aa.w, Ab.x, Ab.y, Ab.z, Ab.w};
        float g[HID] = {ga.x, ga.y, ga.z, ga.w, gb2.x, gb2.y, gb2.z, gb2.w};
        float wg[HID], a16[HID];
#pragma unroll
        for (int i = 0; i < HID; i++) {
            wg[i] = win[i] * g[i];
            float a2 = A[i]*A[i], a4 = a2*a2, a8 = a4*a4;
            a16[i] = a8*a8;
        }
        const float4* xv = (const float4*)(xb + t);
#pragma unroll
        for (int s4 = 0; s4 < 4; s4++) {
            float4 xq = xv[s4];
            float xsv[4] = {xq.x, xq.y, xq.z, xq.w};
#pragma unroll
            for (int s = 0; s < 4; s++)
#pragma unroll
                for (int i = 0; i < HID; i++)
                    c[i] = fmaf(A[i], c[i], xsv[s] * wg[i]);
        }
#pragma unroll
        for (int i = 0; i < HID; i++) P[i] *= a16[i];
    }
    const size_t base = ((size_t)b * NCH + ch) * HID;
#pragma unroll
    for (int i = 0; i < HID; i++) { d_P[base + i] = P[i]; d_c[base + i] = c[i]; }
}

__global__ void __launch_bounds__(256) scan_kernel() {
    int gw   = (blockIdx.x * blockDim.x + threadIdx.x) >> 5;
    int lane = threadIdx.x & 31;
    int b = gw >> 3, i = gw & 7;
    const int S = NCH / 32;
    float P[S], c[S];
#pragma unroll
    for (int s = 0; s < S; s++) {
        size_t idx = ((size_t)b * NCH + (lane * S + s)) * HID + i;
        P[s] = d_P[idx]; c[s] = d_c[idx];
    }
    float Pt = 1.0f, ct = 0.0f;
#pragma unroll
    for (int s = 0; s < S; s++) { ct = fmaf(P[s], ct, c[s]); Pt *= P[s]; }
#pragma unroll
    for (int off = 1; off < 32; off <<= 1) {
        float Pp = __shfl_up_sync(0xffffffffu, Pt, off);
        float cp = __shfl_up_sync(0xffffffffu, ct, off);
        if (lane >= off) { ct = fmaf(Pt, cp, ct); Pt *= Pp; }
    }
    float h = __shfl_up_sync(0xffffffffu, ct, 1);
    if (lane == 0) h = 0.0f;
#pragma unroll
    for (int s = 0; s < S; s++) {
        size_t idx = ((size_t)b * NCH + (lane * S + s)) * HID + i;
        d_H0[idx] = h;
        h = fmaf(P[s], h, c[s]);
    }
}

__global__ void __launch_bounds__(256) pass2_kernel(
    const float* __restrict__ x, const float* __restrict__ w_in,
    const float* __restrict__ w_out, float* __restrict__ y)
{
    int q = blockIdx.x * blockDim.x + threadIdx.x;
    if (q >= BB * NCH) return;
    int b = q / NCH, ch = q % NCH;
    float win[HID], wo[HID], h[HID];
#pragma unroll
    for (int i = 0; i < HID; i++) {
        win[i] = w_in[i]; wo[i] = w_out[i];
        h[i] = d_H0[((size_t)b * NCH + ch) * HID + i];
    }
    const int t0 = ch * CCH;
    const float* xb = x + (size_t)b * TT;
    float* yb = y + (size_t)b * TT;
#pragma unroll 1
    for (int blk = 0; blk < CCH / 16; blk++) {
        int t = t0 + blk * 16;
        int j = (t >> 4) - 1; if (j < 0) j = 0;
        const float4* ap = (const float4*)(d_As + ((size_t)b * FF + j) * HID);
        const float4* gp = (const float4*)(d_gs + ((size_t)b * FF + j) * HID);
        float4 Aa = ap[0], Ab = ap[1], ga = gp[0], gb2 = gp[1];
        float A[HID] = {Aa.x, Aa.y, Aa.z, Aa.w, Ab.x, Ab.y, Ab.z, Ab.w};
        float g[HID] = {ga.x, ga.y, ga.z, ga.w, gb2.x, gb2.y, gb2.z, gb2.w};
        float wg[HID];
#pragma unroll
        for (int i = 0; i < HID; i++) wg[i] = win[i] * g[i];
        const float4* xv = (const float4*)(xb + t);
#pragma unroll
        for (int s4 = 0; s4 < 4; s4++) {
            float4 xq = xv[s4];
            float xsv[4] = {xq.x, xq.y, xq.z, xq.w};
#pragma unroll
            for (int s = 0; s < 4; s++) {
#pragma unroll
                for (int i = 0; i < HID; i++)
                    h[i] = fmaf(A[i], h[i], xsv[s] * wg[i]);
                float yv = 0.0f;
#pragma unroll
                for (int i = 0; i < HID; i++) yv = fmaf(h[i], wo[i], yv);
                yb[t + s4 * 4 + s] = yv;
            }
        }
    }
}

extern "C" void kernel_launch(void* const* d_in, const int* in_sizes, int n_in,
                              void* d_out, int out_size) {
    const float* x    = (const float*)d_in[0];
    const float* w_in = (const float*)d_in[1];
    const float* w_out= (const float*)d_in[2];
    const float* w_ih = (const float*)d_in[3];
    const float* w_hh = (const float*)d_in[4];
    const float* b_ih = (const float*)d_in[5];
    const float* b_hh = (const float*)d_in[6];
    const float* w_sl = (const float*)d_in[7];
    const float* b_sl = (const float*)d_in[8];
    float* y = (float*)d_out;

    static int configured = 0;
    if (!configured) {
        cudaFuncSetAttribute(slow_wmma_kernel,
                             cudaFuncAttributeMaxDynamicSharedMemorySize, SM_BYTES);
        configured = 1;
    }

    init_cpar_kernel<<<1, GH>>>(w_ih, b_ih, b_hh);
    slow_wmma_kernel<<<2048, 256, SM_BYTES>>>(x, w_hh, w_sl, b_sl);
    pass1_kernel<<<(BB * NCH) / 256, 256>>>(x, w_in);
    scan_kernel<<<(BB * HID * 32) / 256, 256>>>();
    pass2_kernel<<<(BB * NCH) / 256, 256>>>(x, w_in, w_out, y);
}

// round 14
// speedup vs baseline: 9.6033x; 1.2778x over previous
#include <cuda_runtime.h>
#include <cuda_fp16.h>
#include <mma.h>
#include <math.h>
#include <stdint.h>

using namespace nvcuda;

#define BB   128
#define TT   65536
#define DELTA 16
#define LS   32
#define HID  8
#define GH   64
#define ODIM 16
#define FF   4095
#define CCH  64
#define NCH  (TT/CCH)

typedef unsigned int u32;

// ---------------- device scratch ----------------
__device__ float d_As[(size_t)BB * FF * HID];
__device__ float d_gs[(size_t)BB * FF * HID];
__device__ float d_P [BB * NCH * HID];
__device__ float d_c [BB * NCH * HID];
__device__ float d_H0[BB * NCH * HID];
__device__ float d_cpar[GH * 8];

__device__ __forceinline__ float sigf(float v) {
    return __fdividef(1.0f, 1.0f + __expf(-v));
}
__device__ __forceinline__ float tanh_ap(float v) {
    float r; asm("tanh.approx.f32 %0, %1;" : "=f"(r) : "f"(v)); return r;
}
__device__ __forceinline__ float sig_ap(float v) {
    return fmaf(tanh_ap(0.5f * v), 0.5f, 0.5f);
}

__global__ void init_cpar_kernel(const float* __restrict__ w_ih,
                                 const float* __restrict__ b_ih,
                                 const float* __restrict__ b_hh) {
    int j = threadIdx.x;
    if (j < GH) {
        d_cpar[j*8+0] = w_ih[j];
        d_cpar[j*8+1] = w_ih[GH + j];
        d_cpar[j*8+2] = w_ih[2*GH + j];
        d_cpar[j*8+3] = b_ih[j]      + b_hh[j];
        d_cpar[j*8+4] = b_ih[GH + j] + b_hh[GH + j];
        d_cpar[j*8+5] = b_ih[2*GH + j];
        d_cpar[j*8+6] = b_hh[2*GH + j];
        d_cpar[j*8+7] = 0.0f;
    }
}

// ---------------- smem layout (bytes) ----------------
#define LDW   72
#define LDHH  264
#define LDS_X 33
#define SM_WHI  0
#define SM_H    (SM_WHI + 192*LDW*2)         // 27648
#define SM_XS   (SM_H + 64*LDHH*2)           // 61440
#define SM_CPAR (SM_XS + 256*LDS_X*4)        // 95232
#define SM_WSL  (SM_CPAR + GH*8*4)           // 97280
#define SM_BSL  (SM_WSL + ODIM*GH*4)         // 101376
#define SM_BYTES (SM_BSL + 64)               // 101440  (x2 = 202,880 fits 228KB/SM)

// grid = 2048 CTAs, 256 threads, 2 CTAs/SM. CTA covers frames {2c, 2c+1} x 128 rows.
__global__ void __launch_bounds__(256, 2) slow_wmma_kernel(
    const float* __restrict__ x,
    const float* __restrict__ w_hh,
    const float* __restrict__ w_sl,
    const float* __restrict__ b_sl)
{
    extern __shared__ char sm[];
    const int tid  = threadIdx.x;
    const int wid  = tid >> 5;
    const int f0   = blockIdx.x * 2;
    const int cb   = wid * 32;

    __half* WHI = (__half*)(sm + SM_WHI);
    __half* HS  = (__half*)(sm + SM_H);
    float* xs     = (float*)(sm + SM_XS);
    float* cparsm = (float*)(sm + SM_CPAR);
    float* wslsm  = (float*)(sm + SM_WSL);
    float* bslsm  = (float*)(sm + SM_BSL);

    // ---- probe wmma accumulator element->(row,col) mapping ----
    int jm[8], cm[8];
    {
        __half* pA = (__half*)(sm + SM_XS);
        __half* pB = pA + 256;
        if (tid < 256) {
            int r = tid >> 4, k = tid & 15;
            pA[tid] = __float2half_rn(r == k ? 1.0f : 0.0f);
            pB[tid] = __float2half_rn((float)tid);
        }
        __syncthreads();
        wmma::fragment<wmma::matrix_a, 16,16,16, __half, wmma::row_major> pa;
        wmma::fragment<wmma::matrix_b, 16,16,16, __half, wmma::row_major> pb;
        wmma::fragment<wmma::accumulator, 16,16,16, float> pc;
        wmma::load_matrix_sync(pa, pA, 16);
        wmma::load_matrix_sync(pb, pB, 16);
        wmma::fill_fragment(pc, 0.0f);
        wmma::mma_sync(pc, pa, pb, pc);
#pragma unroll
        for (int e = 0; e < 8; e++) {
            int v = (int)(pc.x[e] + 0.5f);
            jm[e] = v >> 4;
            cm[e] = v & 15;
        }
        __syncthreads();
    }

    // ---- prologue ----
    for (int i = tid; i < 192 * GH; i += 256) {
        int g = i >> 6, k = i & 63;
        WHI[g * LDW + k] = __float2half_rn(w_hh[i]);
    }
    for (int i = tid; i < (64 * LDHH * 2) / 4; i += 256)
        ((u32*)(sm + SM_H))[i] = 0u;
    {
        int c = tid;
        int b = c & 127;
        int f = f0 + (c >> 7); if (f > FF - 1) f = FF - 1;
        const float* xp = x + (size_t)b * TT + (size_t)f * DELTA;
#pragma unroll
        for (int t = 0; t < LS; t++) xs[c * LDS_X + t] = xp[t];
    }
    for (int i = tid; i < GH * 8;    i += 256) cparsm[i] = d_cpar[i];
    for (int i = tid; i < ODIM * GH; i += 256) wslsm[i]  = w_sl[i];
    if (tid < ODIM) bslsm[tid] = b_sl[tid];
    __syncthreads();

    // ---- 32 GRU steps ----
#pragma unroll 1
    for (int t = 0; t < LS; t++) {
        float xts[16];
#pragma unroll
        for (int e = 0; e < 8; e++) {
            xts[e]     = xs[(cb + cm[e]) * LDS_X + t];
            xts[8 + e] = xs[(cb + 16 + cm[e]) * LDS_X + t];
        }

        wmma::fragment<wmma::matrix_b, 16,16,16, __half, wmma::row_major> bF[4][2];
#pragma unroll
        for (int kt = 0; kt < 4; kt++)
#pragma unroll
            for (int nt = 0; nt < 2; nt++)
                wmma::load_matrix_sync(bF[kt][nt], HS + (size_t)(kt*16) * LDHH + cb + nt*16, LDHH);

#pragma unroll 1
        for (int mg = 0; mg < 4; mg++) {
            wmma::fragment<wmma::accumulator, 16,16,16, float> acc[3][2];
#pragma unroll
            for (int kind = 0; kind < 3; kind++)
#pragma unroll
                for (int nt = 0; nt < 2; nt++)
                    wmma::fill_fragment(acc[kind][nt], 0.0f);

#pragma unroll
            for (int kind = 0; kind < 3; kind++) {
                const int mi = kind * 4 + mg;
#pragma unroll
                for (int kt = 0; kt < 4; kt++) {
                    wmma::fragment<wmma::matrix_a, 16,16,16, __half, wmma::row_major> aHI;
                    wmma::load_matrix_sync(aHI, WHI + (size_t)(mi*16) * LDW + kt*16, LDW);
                    wmma::mma_sync(acc[kind][0], aHI, bF[kt][0], acc[kind][0]);
                    wmma::mma_sync(acc[kind][1], aHI, bF[kt][1], acc[kind][1]);
                }
            }

            // fragment-direct epilogue; all nonlinearities via MUFU.TANH
#pragma unroll
            for (int e = 0; e < 8; e++) {
                const int j = mg * 16 + jm[e];
                const float4 c0 = ((const float4*)(cparsm + j * 8))[0];
                const float4 c1 = ((const float4*)(cparsm + j * 8))[1];
#pragma unroll
                for (int nt = 0; nt < 2; nt++) {
                    const int c = cb + nt * 16 + cm[e];
                    const float xt = xts[nt * 8 + e];
                    float gr = acc[0][nt].x[e];
                    float gz = acc[1][nt].x[e];
                    float gn = acc[2][nt].x[e];

                    float ho = __half2float(HS[(size_t)j * LDHH + c]);

                    float r = sig_ap(gr + fmaf(xt, c0.x, c0.w));
                    float z = sig_ap(gz + fmaf(xt, c0.y, c1.x));
                    float n = tanh_ap(fmaf(xt, c0.z, c1.y) + r * (gn + c1.z));
                    float h = n + z * (ho - n);

                    HS[(size_t)j * LDHH + c] = __float2half_rn(h);
                }
            }
        }
        __syncwarp();
    }

    // ---- final projection (accurate sigmoid) ----
    {
        const int c = tid;
        const int b = c & 127;
        const int f = f0 + (c >> 7);
        if (f < FF) {
            float hv[GH];
#pragma unroll
            for (int k = 0; k < GH; k++)
                hv[k] = __half2float(HS[(size_t)k * LDHH + c]);
            const size_t ob = ((size_t)b * FF + f) * HID;
#pragma unroll 1
            for (int o = 0; o < HID; o++) {
                float a0 = bslsm[o];
                float a1 = bslsm[HID + o];
#pragma unroll
                for (int k = 0; k < GH; k++) {
                    a0 = fmaf(wslsm[o * GH + k], hv[k], a0);
                    a1 = fmaf(wslsm[(HID + o) * GH + k], hv[k], a1);
                }
                d_As[ob + o] = sigf(a0);
                d_gs[ob + o] = a1;
            }
        }
    }
}

// ---------------- fast branch ----------------
__global__ void __launch_bounds__(256) pass1_kernel(
    const float* __restrict__ x, const float* __restrict__ w_in)
{
    int q = blockIdx.x * blockDim.x + threadIdx.x;
    if (q >= BB * NCH) return;
    int b = q / NCH, ch = q % NCH;
    float win[HID], P[HID], c[HID];
#pragma unroll
    for (int i = 0; i < HID; i++) { win[i] = w_in[i]; P[i] = 1.0f; c[i] = 0.0f; }
    const int t0 = ch * CCH;
    const float* xb = x + (size_t)b * TT;
#pragma unroll 1
    for (int blk = 0; blk < CCH / 16; blk++) {
        int t = t0 + blk * 16;
        int j = (t >> 4) - 1; if (j < 0) j = 0;
        const float4* ap = (const float4*)(d_As + ((size_t)b * FF + j) * HID);
        const float4* gp = (const float4*)(d_gs + ((size_t)b * FF + j) * HID);
        float4 Aa = ap[0], Ab = ap[1], ga = gp[0], gb2 = gp[1];
        float A[HID] = {Aa.x, Aa.y, Aa.z, Aa.w, Ab.x, Ab.y, Ab.z, Ab.w};
        float g[HID] = {ga.x, ga.y, ga.z, ga.w, gb2.x, gb2.y, gb2.z, gb2.w};
        float wg[HID], a16[HID];
#pragma unroll
        for (int i = 0; i < HID; i++) {
            wg[i] = win[i] * g[i];
            float a2 = A[i]*A[i], a4 = a2*a2, a8 = a4*a4;
            a16[i] = a8*a8;
        }
        const float4* xv = (const float4*)(xb + t);
#pragma unroll
        for (int s4 = 0; s4 < 4; s4++) {
            float4 xq = xv[s4];
            float xsv[4] = {xq.x, xq.y, xq.z, xq.w};
#pragma unroll
            for (int s = 0; s < 4; s++)
#pragma unroll
                for (int i = 0; i < HID; i++)
                    c[i] = fmaf(A[i], c[i], xsv[s] * wg[i]);
        }
#pragma unroll
        for (int i = 0; i < HID; i++) P[i] *= a16[i];
    }
    const size_t base = ((size_t)b * NCH + ch) * HID;
#pragma unroll
    for (int i = 0; i < HID; i++) { d_P[base + i] = P[i]; d_c[base + i] = c[i]; }
}

__global__ void __launch_bounds__(256) scan_kernel() {
    int gw   = (blockIdx.x * blockDim.x + threadIdx.x) >> 5;
    int lane = threadIdx.x & 31;
    int b = gw >> 3, i = gw & 7;
    const int S = NCH / 32;
    float P[S], c[S];
#pragma unroll
    for (int s = 0; s < S; s++) {
        size_t idx = ((size_t)b * NCH + (lane * S + s)) * HID + i;
        P[s] = d_P[idx]; c[s] = d_c[idx];
    }
    float Pt = 1.0f, ct = 0.0f;
#pragma unroll
    for (int s = 0; s < S; s++) { ct = fmaf(P[s], ct, c[s]); Pt *= P[s]; }
#pragma unroll
    for (int off = 1; off < 32; off <<= 1) {
        float Pp = __shfl_up_sync(0xffffffffu, Pt, off);
        float cp = __shfl_up_sync(0xffffffffu, ct, off);
        if (lane >= off) { ct = fmaf(Pt, cp, ct); Pt *= Pp; }
    }
    float h = __shfl_up_sync(0xffffffffu, ct, 1);
    if (lane == 0) h = 0.0f;
#pragma unroll
    for (int s = 0; s < S; s++) {
        size_t idx = ((size_t)b * NCH + (lane * S + s)) * HID + i;
        d_H0[idx] = h;
        h = fmaf(P[s], h, c[s]);
    }
}

__global__ void __launch_bounds__(256) pass2_kernel(
    const float* __restrict__ x, const float* __restrict__ w_in,
    const float* __restrict__ w_out, float* __restrict__ y)
{
    int q = blockIdx.x * blockDim.x + threadIdx.x;
    if (q >= BB * NCH) return;
    int b = q / NCH, ch = q % NCH;
    float win[HID], wo[HID], h[HID];
#pragma unroll
    for (int i = 0; i < HID; i++) {
        win[i] = w_in[i]; wo[i] = w_out[i];
        h[i] = d_H0[((size_t)b * NCH + ch) * HID + i];
    }
    const int t0 = ch * CCH;
    const float* xb = x + (size_t)b * TT;
    float* yb = y + (size_t)b * TT;
#pragma unroll 1
    for (int blk = 0; blk < CCH / 16; blk++) {
        int t = t0 + blk * 16;
        int j = (t >> 4) - 1; if (j < 0) j = 0;
        const float4* ap = (const float4*)(d_As + ((size_t)b * FF + j) * HID);
        const float4* gp = (const float4*)(d_gs + ((size_t)b * FF + j) * HID);
        float4 Aa = ap[0], Ab = ap[1], ga = gp[0], gb2 = gp[1];
        float A[HID] = {Aa.x, Aa.y, Aa.z, Aa.w, Ab.x, Ab.y, Ab.z, Ab.w};
        float g[HID] = {ga.x, ga.y, ga.z, ga.w, gb2.x, gb2.y, gb2.z, gb2.w};
        float wg[HID];
#pragma unroll
        for (int i = 0; i < HID; i++) wg[i] = win[i] * g[i];
        const float4* xv = (const float4*)(xb + t);
#pragma unroll
        for (int s4 = 0; s4 < 4; s4++) {
            float4 xq = xv[s4];
            float xsv[4] = {xq.x, xq.y, xq.z, xq.w};
#pragma unroll
            for (int s = 0; s < 4; s++) {
#pragma unroll
                for (int i = 0; i < HID; i++)
                    h[i] = fmaf(A[i], h[i], xsv[s] * wg[i]);
                float yv = 0.0f;
#pragma unroll
                for (int i = 0; i < HID; i++) yv = fmaf(h[i], wo[i], yv);
                yb[t + s4 * 4 + s] = yv;
            }
        }
    }
}

extern "C" void kernel_launch(void* const* d_in, const int* in_sizes, int n_in,
                              void* d_out, int out_size) {
    const float* x    = (const float*)d_in[0];
    const float* w_in = (const float*)d_in[1];
    const float* w_out= (const float*)d_in[2];
    const float* w_ih = (const float*)d_in[3];
    const float* w_hh = (const float*)d_in[4];
    const float* b_ih = (const float*)d_in[5];
    const float* b_hh = (const float*)d_in[6];
    const float* w_sl = (const float*)d_in[7];
    const float* b_sl = (const float*)d_in[8];
    float* y = (float*)d_out;

    static int configured = 0;
    if (!configured) {
        cudaFuncSetAttribute(slow_wmma_kernel,
                             cudaFuncAttributeMaxDynamicSharedMemorySize, SM_BYTES);
        configured = 1;
    }

    init_cpar_kernel<<<1, GH>>>(w_ih, b_ih, b_hh);
    slow_wmma_kernel<<<2048, 256, SM_BYTES>>>(x, w_hh, w_sl, b_sl);
    pass1_kernel<<<(BB * NCH) / 256, 256>>>(x, w_in);
    scan_kernel<<<(BB * HID * 32) / 256, 256>>>();
    pass2_kernel<<<(BB * NCH) / 256, 256>>>(x, w_in, w_out, y);
}